// round 7
// baseline (speedup 1.0000x reference)
#include <cuda_runtime.h>
#include <cuda_bf16.h>
#include <cstdint>

#define N_NODES 100000
#define N_GRAPHS 64
#define MAX_E    1600000
#define SCAN_B   1024
#define N_SCANB  ((N_NODES + SCAN_B - 1) / SCAN_B)   // 98

// ---------------- scratch (device globals; no allocation allowed) ----------
__device__ int   g_flag64;               // 1 if index buffers are int64
__device__ int   g_batch[N_NODES];
__device__ int   g_indeg[N_NODES];
__device__ float g_dinv[N_NODES];
__device__ int   g_row_ptr[N_NODES + 1];
__device__ int   g_cur[N_NODES];
__device__ unsigned long long g_scan_flag[N_SCANB];   // hi32: status(1=agg,2=pref), lo32: value
__device__ __align__(16) int2   g_csr[MAX_E];          // {src, nrm as int}
__device__ __align__(16) float4 g_pos4[N_NODES];       // padded pos
__device__ __align__(16) float  g_h[N_NODES * 64];     // h1 activations
__device__ __align__(16) float  g_y[N_NODES * 32];     // layer-3 pre-agg (stride 32, 24 used)
__device__ float g_sums[N_GRAPHS * 24];
__device__ float g_cnt[N_GRAPHS];

// ---------------- detect dtype + zero indeg/pool/scan-state ------------------
// int64 indices (< 2^31) => every odd 32-bit word is zero. 2048 samples.
__global__ void detect_zero_kernel(const int* __restrict__ buf, int samples) {
    int t = threadIdx.x;
    int v = blockIdx.x * blockDim.x + t;
    if (v < N_NODES) g_indeg[v] = 0;
    if (blockIdx.x == 0) {
        __shared__ int s_nz[256];
        int nz = 0;
        for (int i = t; i < samples; i += 256) nz |= buf[2 * i + 1];
        s_nz[t] = nz;
        __syncthreads();
        for (int off = 128; off > 0; off >>= 1) {
            if (t < off) s_nz[t] |= s_nz[t + off];
            __syncthreads();
        }
        if (t == 0) g_flag64 = (s_nz[0] == 0) ? 1 : 0;
        for (int i = t; i < N_GRAPHS * 24; i += 256) g_sums[i] = 0.0f;
        if (t < N_GRAPHS) g_cnt[t] = 0.0f;
        if (t < N_SCANB) g_scan_flag[t] = 0ULL;
    }
}

__device__ __forceinline__ int load_idx(const int* __restrict__ buf, long long i) {
    return g_flag64 ? buf[2 * i] : buf[(int)i];
}

// ---------------- prep: batch convert + graph counts + degree + pos4 --------
__global__ void prep_kernel(const int* __restrict__ ei, const int* __restrict__ batch,
                            const float* __restrict__ pos, int E) {
    __shared__ float scnt[N_GRAPHS];
    int t = threadIdx.x;
    int i = blockIdx.x * blockDim.x + t;
    bool node_block = (blockIdx.x * blockDim.x) < N_NODES;   // uniform per block
    if (node_block) {
        if (t < N_GRAPHS) scnt[t] = 0.0f;
        __syncthreads();
    }
    if (i < N_NODES) {
        int g = load_idx(batch, i);
        g_batch[i] = g;
        atomicAdd(&scnt[g], 1.0f);
        g_pos4[i] = make_float4(pos[3 * i], pos[3 * i + 1], pos[3 * i + 2], 0.0f);
    }
    if (i < E) {
        int d = load_idx(ei, (long long)E + i);
        atomicAdd(&g_indeg[d], 1);
    }
    if (node_block) {
        __syncthreads();
        if (t < N_GRAPHS && scnt[t] != 0.0f) atomicAdd(&g_cnt[t], scnt[t]);
    }
}

// ---------------- single-pass scan: indeg -> row_ptr/cur (+ dinv) -------------
// Decoupled lookback, 98 blocks (all co-resident: 296-block capacity).
__global__ void __launch_bounds__(SCAN_B)
scan_kernel(int E) {
    __shared__ int warp_x[32];
    __shared__ int s_prefix;
    int t = threadIdx.x, b = blockIdx.x;
    int lane = t & 31, wid = t >> 5;
    int i = b * SCAN_B + t;
    int v = (i < N_NODES) ? g_indeg[i] : 0;
    if (i < N_NODES) g_dinv[i] = rsqrtf((float)(v + 1));   // +1 self-loop
    // warp inclusive scan
    int x = v;
#pragma unroll
    for (int off = 1; off < 32; off <<= 1) {
        int y = __shfl_up_sync(0xFFFFFFFFu, x, off);
        if (lane >= off) x += y;
    }
    if (lane == 31) warp_x[wid] = x;
    __syncthreads();
    if (wid == 0) {
        int w = warp_x[lane];
        int xs = w;
#pragma unroll
        for (int off = 1; off < 32; off <<= 1) {
            int y = __shfl_up_sync(0xFFFFFFFFu, xs, off);
            if (lane >= off) xs += y;
        }
        warp_x[lane] = xs - w;   // exclusive warp offsets
        if (lane == 31) {
            // publish aggregate (block 0 publishes final prefix immediately)
            unsigned long long st = (b == 0) ? 2ULL : 1ULL;
            unsigned long long pkt = (st << 32) | (unsigned int)xs;
            atomicExch(&g_scan_flag[b], pkt);
        }
    }
    __syncthreads();
    int block_incl = x + warp_x[wid];   // inclusive scan within block
    // windowed lookback by warp 0
    if (wid == 0) {
        int prefix = 0;
        if (b > 0) {
            int j = b - 1;
            while (true) {
                int idx = j - lane;
                unsigned long long pkt = (idx >= 0)
                    ? atomicAdd(&g_scan_flag[idx], 0ULL)
                    : (2ULL << 32);                      // below 0: prefix 0
                int st = (int)(pkt >> 32);
                unsigned rdy = __ballot_sync(0xFFFFFFFFu, st != 0);
                if (rdy != 0xFFFFFFFFu) continue;        // retry window
                unsigned pm = __ballot_sync(0xFFFFFFFFu, st == 2);
                int stop = pm ? (__ffs(pm) - 1) : 32;    // nearest prefix-ready
                int val = (lane <= stop) ? (int)(unsigned int)pkt : 0;
#pragma unroll
                for (int off = 16; off > 0; off >>= 1)
                    val += __shfl_down_sync(0xFFFFFFFFu, val, off);
                prefix += __shfl_sync(0xFFFFFFFFu, val, 0);
                if (stop < 32) break;
                j -= 32;
            }
        }
        if (lane == 0) s_prefix = prefix;
    }
    __syncthreads();
    int prefix = s_prefix;
    if (t == SCAN_B - 1) {   // publish final prefix for successors
        unsigned long long pkt = (2ULL << 32) | (unsigned int)(prefix + block_incl);
        atomicExch(&g_scan_flag[b], pkt);
    }
    int excl = prefix + block_incl - v;
    if (i < N_NODES) {
        g_row_ptr[i] = excl;
        g_cur[i] = excl;
    }
    if (i == N_NODES) g_row_ptr[N_NODES] = E;
}

// ---------------- CSR fill ----------------------------------------------------
__global__ void fill_csr_kernel(const int* __restrict__ ei, int E) {
    int e = blockIdx.x * blockDim.x + threadIdx.x;
    if (e >= E) return;
    int s = load_idx(ei, e);
    int d = load_idx(ei, (long long)E + e);
    int pos = atomicAdd(&g_cur[d], 1);
    float nrm = g_dinv[s] * g_dinv[d];
    g_csr[pos] = make_int2(s, __float_as_int(nrm));
}

// ---------------- layer 1: gather(pos4) + GEMM 3->64 + ReLU ------------------
__global__ void __launch_bounds__(128)
layer1_kernel(const float* __restrict__ W1, const float* __restrict__ b1,
              float* __restrict__ h1) {
    __shared__ float sW[3 * 64];
    __shared__ float sb[64];
    for (int i = threadIdx.x; i < 3 * 64; i += 128) sW[i] = W1[i];
    if (threadIdx.x < 64) sb[threadIdx.x] = b1[threadIdx.x];
    __syncthreads();
    int v = blockIdx.x * 128 + threadIdx.x;
    if (v >= N_NODES) return;
    float di = g_dinv[v];
    float self = di * di;
    float4 pv = g_pos4[v];
    float a0 = self * pv.x;
    float a1 = self * pv.y;
    float a2 = self * pv.z;
    int e = g_row_ptr[v], end = g_row_ptr[v + 1];
    for (; e + 2 <= end; e += 2) {
        int2 p0 = g_csr[e], p1 = g_csr[e + 1];
        float4 f0 = g_pos4[p0.x];
        float4 f1 = g_pos4[p1.x];
        float n0 = __int_as_float(p0.y), n1 = __int_as_float(p1.y);
        a0 = fmaf(n0, f0.x, a0); a1 = fmaf(n0, f0.y, a1); a2 = fmaf(n0, f0.z, a2);
        a0 = fmaf(n1, f1.x, a0); a1 = fmaf(n1, f1.y, a1); a2 = fmaf(n1, f1.z, a2);
    }
    if (e < end) {
        int2 p = g_csr[e];
        float4 f = g_pos4[p.x];
        float nrm = __int_as_float(p.y);
        a0 = fmaf(nrm, f.x, a0); a1 = fmaf(nrm, f.y, a1); a2 = fmaf(nrm, f.z, a2);
    }
    float* o = h1 + (long long)v * 64;
#pragma unroll
    for (int j4 = 0; j4 < 16; j4++) {
        float4 r;
        float* rr = (float*)&r;
#pragma unroll
        for (int u = 0; u < 4; u++) {
            int j = j4 * 4 + u;
            float acc = sb[j];
            acc = fmaf(a0, sW[j], acc);
            acc = fmaf(a1, sW[64 + j], acc);
            acc = fmaf(a2, sW[128 + j], acc);
            rr[u] = fmaxf(acc, 0.0f);
        }
        *(float4*)(o + j4 * 4) = r;
    }
}

// ---------------- layer 2+3: gather(h1,64) + GEMM64x64 + ReLU + GEMM64x24 -----
// Half-warp per node: lane owns a float4 of features (16 lanes x 4 = 64).
#define L2_NPB 64   // nodes per block: 8 warps x 2 nodes x 4 iterations
__global__ void __launch_bounds__(256)
layer2_kernel(const float* __restrict__ h1, const float* __restrict__ W2,
              const float* __restrict__ b2, const float* __restrict__ W3,
              float* __restrict__ y) {
    __shared__ float sW2[64 * 64];
    __shared__ float sW3[64 * 24];
    __shared__ float sb2[64];
    __shared__ float tile[16][64];
    int t = threadIdx.x;
    for (int i = t; i < 64 * 64; i += 256) sW2[i] = W2[i];
    for (int i = t; i < 64 * 24; i += 256) sW3[i] = W3[i];
    if (t < 64) sb2[t] = b2[t];
    __syncthreads();
    int warp = t >> 5, lane = t & 31;
    int half = lane >> 4, q = lane & 15;
#pragma unroll
    for (int it = 0; it < L2_NPB / 16; it++) {
        int vbase = blockIdx.x * L2_NPB + it * 16 + warp * 2;
        int v = vbase + half;
        // ---- gather phase (half-warp per node, float4 per lane, 4-wide MLP) ----
        float4 a = make_float4(0.0f, 0.0f, 0.0f, 0.0f);
        if (v < N_NODES) {
            float di = g_dinv[v];
            float self = di * di;
            float4 x = ((const float4*)(h1 + (long long)v * 64))[q];
            a.x = self * x.x; a.y = self * x.y; a.z = self * x.z; a.w = self * x.w;
            int e = g_row_ptr[v], end = g_row_ptr[v + 1];
            for (; e + 4 <= end; e += 4) {
                int2 p[4];
                float4 f[4];
#pragma unroll
                for (int u = 0; u < 4; u++) p[u] = g_csr[e + u];
#pragma unroll
                for (int u = 0; u < 4; u++)
                    f[u] = ((const float4*)(h1 + (long long)p[u].x * 64))[q];
#pragma unroll
                for (int u = 0; u < 4; u++) {
                    float n = __int_as_float(p[u].y);
                    a.x = fmaf(n, f[u].x, a.x); a.y = fmaf(n, f[u].y, a.y);
                    a.z = fmaf(n, f[u].z, a.z); a.w = fmaf(n, f[u].w, a.w);
                }
            }
            for (; e < end; e++) {
                int2 p = g_csr[e];
                float4 f = ((const float4*)(h1 + (long long)p.x * 64))[q];
                float n = __int_as_float(p.y);
                a.x = fmaf(n, f.x, a.x); a.y = fmaf(n, f.y, a.y);
                a.z = fmaf(n, f.z, a.z); a.w = fmaf(n, f.w, a.w);
            }
        }
        ((float4*)tile[warp * 2 + half])[q] = a;
        __syncwarp();
        // ---- GEMM phase: warp handles its 2 nodes sequentially ----
#pragma unroll
        for (int s = 0; s < 2; s++) {
            int vv = vbase + s;
            if (vv >= N_NODES) continue;
            float* row = tile[warp * 2 + s];
            float c0 = sb2[lane], c1 = sb2[lane + 32];
#pragma unroll
            for (int k = 0; k < 64; k++) {
                float xk = row[k];
                c0 = fmaf(xk, sW2[k * 64 + lane], c0);
                c1 = fmaf(xk, sW2[k * 64 + lane + 32], c1);
            }
            c0 = fmaxf(c0, 0.0f);
            c1 = fmaxf(c1, 0.0f);
            __syncwarp();
            row[lane] = c0;
            row[lane + 32] = c1;
            __syncwarp();
            if (lane < 24) {
                float acc = 0.0f;
#pragma unroll
                for (int k = 0; k < 64; k++)
                    acc = fmaf(row[k], sW3[k * 24 + lane], acc);
                y[(long long)vv * 32 + lane] = acc;
            }
            __syncwarp();
        }
    }
}

// ---------------- layer 3 aggregate (dim 24, stride 32) + fused pooling -------
__global__ void __launch_bounds__(256)
gather24_pool_kernel(const float* __restrict__ y) {
    int gtid = blockIdx.x * blockDim.x + threadIdx.x;
    int v = gtid >> 5;
    int lane = gtid & 31;
    if (v >= N_NODES || lane >= 24) return;
    float di = g_dinv[v];
    float self = di * di;
    float a = self * y[(long long)v * 32 + lane];
    int e = g_row_ptr[v], end = g_row_ptr[v + 1];
    for (; e + 4 <= end; e += 4) {
        int2 p0 = g_csr[e], p1 = g_csr[e + 1], p2 = g_csr[e + 2], p3 = g_csr[e + 3];
        float x0 = y[(long long)p0.x * 32 + lane];
        float x1 = y[(long long)p1.x * 32 + lane];
        float x2 = y[(long long)p2.x * 32 + lane];
        float x3 = y[(long long)p3.x * 32 + lane];
        a = fmaf(__int_as_float(p0.y), x0, a);
        a = fmaf(__int_as_float(p1.y), x1, a);
        a = fmaf(__int_as_float(p2.y), x2, a);
        a = fmaf(__int_as_float(p3.y), x3, a);
    }
    for (; e < end; e++) {
        int2 p = g_csr[e];
        a = fmaf(__int_as_float(p.y), y[(long long)p.x * 32 + lane], a);
    }
    int g = g_batch[v];
    atomicAdd(&g_sums[g * 24 + lane], a);
}

// ---------------- final: mean + bias + tanh -----------------------------------
__global__ void final_kernel(const float* __restrict__ b3, float* __restrict__ out) {
    int i = blockIdx.x * blockDim.x + threadIdx.x;
    if (i >= N_GRAPHS * 24) return;
    int g = i / 24;
    int j = i % 24;
    float c = g_cnt[g];
    float m = (c > 0.0f) ? (g_sums[i] / c + b3[j]) : 0.0f;
    out[i] = tanhf(m);
}

// ---------------- launch -----------------------------------------------------
extern "C" void kernel_launch(void* const* d_in, const int* in_sizes, int n_in,
                              void* d_out, int out_size) {
    const float* pos   = (const float*)d_in[0];
    const int*   ei    = (const int*)d_in[1];   // int32 or int64 (detected)
    const int*   batch = (const int*)d_in[2];
    const float* W1    = (const float*)d_in[3];
    const float* b1    = (const float*)d_in[4];
    const float* W2    = (const float*)d_in[5];
    const float* b2    = (const float*)d_in[6];
    const float* W3    = (const float*)d_in[7];
    const float* b3    = (const float*)d_in[8];
    float*       out   = (float*)d_out;

    const int E = in_sizes[1] / 2;

    float* h1; cudaGetSymbolAddress((void**)&h1, g_h);
    float* y;  cudaGetSymbolAddress((void**)&y, g_y);

    const int TB = 256;
    auto grid = [&](long long n, int tb) { return (int)((n + tb - 1) / tb); };

    detect_zero_kernel<<<grid(N_NODES, TB), TB>>>(ei, E < 2048 ? E : 2048);   // #1
    prep_kernel<<<grid(E, TB), TB>>>(ei, batch, pos, E);                      // #2
    scan_kernel<<<N_SCANB, SCAN_B>>>(E);                                      // #3
    fill_csr_kernel<<<grid(E, TB), TB>>>(ei, E);                              // #4 (profiled)
    layer1_kernel<<<grid(N_NODES, 128), 128>>>(W1, b1, h1);                   // #5
    layer2_kernel<<<grid(N_NODES, L2_NPB), 256>>>(h1, W2, b2, W3, y);         // #6
    gather24_pool_kernel<<<grid((long long)N_NODES * 32, TB), TB>>>(y);       // #7
    final_kernel<<<grid(N_GRAPHS * 24, TB), TB>>>(b3, out);                   // #8
}

// round 8
// speedup vs baseline: 1.1433x; 1.1433x over previous
#include <cuda_runtime.h>
#include <cuda_bf16.h>
#include <cstdint>

#define N_NODES 100000
#define N_GRAPHS 64
#define MAX_E    1600000
#define SCAN_B   1024
#define N_SCANB  ((N_NODES + SCAN_B - 1) / SCAN_B)   // 98

// ---------------- scratch (device globals; no allocation allowed) ----------
__device__ int   g_flag64;               // 1 if index buffers are int64
__device__ int   g_batch[N_NODES];
__device__ int   g_indeg[N_NODES];
__device__ float g_dinv[N_NODES];
__device__ int   g_row_ptr[N_NODES + 1];
__device__ int   g_cur[N_NODES];
__device__ unsigned long long g_scan_flag[N_SCANB];   // hi32: status(1=agg,2=pref), lo32: value
__device__ int   g_csr_i[MAX_E];                      // src indices only (norms factored out)
__device__ __align__(16) float4 g_pos4[N_NODES];      // pos, scaled by dinv after scan
__device__ __align__(16) float  g_h[N_NODES * 64];    // scaled h1 activations (dinv*h1)
__device__ __align__(16) float  g_y[N_NODES * 32];    // scaled layer-3 pre-agg (stride 32, 24 used)
__device__ float g_sums[N_GRAPHS * 24];
__device__ float g_cnt[N_GRAPHS];

// ---------------- detect dtype + zero indeg/pool/scan-state ------------------
// int64 indices (< 2^31) => every odd 32-bit word is zero. 2048 samples.
__global__ void detect_zero_kernel(const int* __restrict__ buf, int samples) {
    int t = threadIdx.x;
    int v = blockIdx.x * blockDim.x + t;
    if (v < N_NODES) g_indeg[v] = 0;
    if (blockIdx.x == 0) {
        __shared__ int s_nz[256];
        int nz = 0;
        for (int i = t; i < samples; i += 256) nz |= buf[2 * i + 1];
        s_nz[t] = nz;
        __syncthreads();
        for (int off = 128; off > 0; off >>= 1) {
            if (t < off) s_nz[t] |= s_nz[t + off];
            __syncthreads();
        }
        if (t == 0) g_flag64 = (s_nz[0] == 0) ? 1 : 0;
        for (int i = t; i < N_GRAPHS * 24; i += 256) g_sums[i] = 0.0f;
        if (t < N_GRAPHS) g_cnt[t] = 0.0f;
        if (t < N_SCANB) g_scan_flag[t] = 0ULL;
    }
}

__device__ __forceinline__ int load_idx(const int* __restrict__ buf, long long i) {
    return g_flag64 ? buf[2 * i] : buf[(int)i];
}

// ---------------- prep: batch convert + graph counts + degree + pos4 --------
__global__ void prep_kernel(const int* __restrict__ ei, const int* __restrict__ batch,
                            const float* __restrict__ pos, int E) {
    __shared__ float scnt[N_GRAPHS];
    int t = threadIdx.x;
    int i = blockIdx.x * blockDim.x + t;
    bool node_block = (blockIdx.x * blockDim.x) < N_NODES;   // uniform per block
    if (node_block) {
        if (t < N_GRAPHS) scnt[t] = 0.0f;
        __syncthreads();
    }
    if (i < N_NODES) {
        int g = load_idx(batch, i);
        g_batch[i] = g;
        atomicAdd(&scnt[g], 1.0f);
        g_pos4[i] = make_float4(pos[3 * i], pos[3 * i + 1], pos[3 * i + 2], 0.0f);
    }
    if (i < E) {
        int d = load_idx(ei, (long long)E + i);
        atomicAdd(&g_indeg[d], 1);
    }
    if (node_block) {
        __syncthreads();
        if (t < N_GRAPHS && scnt[t] != 0.0f) atomicAdd(&g_cnt[t], scnt[t]);
    }
}

// ---------------- single-pass scan: indeg -> row_ptr/cur, dinv, scale pos4 ----
// Decoupled lookback, 98 blocks (all co-resident: 296-block capacity).
__global__ void __launch_bounds__(SCAN_B)
scan_kernel(int E) {
    __shared__ int warp_x[32];
    __shared__ int s_prefix;
    int t = threadIdx.x, b = blockIdx.x;
    int lane = t & 31, wid = t >> 5;
    int i = b * SCAN_B + t;
    int v = (i < N_NODES) ? g_indeg[i] : 0;
    float di = 0.0f;
    if (i < N_NODES) {
        di = rsqrtf((float)(v + 1));   // +1 self-loop
        g_dinv[i] = di;
        float4 p = g_pos4[i];          // scale pos in place: p_hat = dinv * pos
        g_pos4[i] = make_float4(di * p.x, di * p.y, di * p.z, 0.0f);
    }
    // warp inclusive scan
    int x = v;
#pragma unroll
    for (int off = 1; off < 32; off <<= 1) {
        int y = __shfl_up_sync(0xFFFFFFFFu, x, off);
        if (lane >= off) x += y;
    }
    if (lane == 31) warp_x[wid] = x;
    __syncthreads();
    if (wid == 0) {
        int w = warp_x[lane];
        int xs = w;
#pragma unroll
        for (int off = 1; off < 32; off <<= 1) {
            int y = __shfl_up_sync(0xFFFFFFFFu, xs, off);
            if (lane >= off) xs += y;
        }
        warp_x[lane] = xs - w;   // exclusive warp offsets
        if (lane == 31) {
            unsigned long long st = (b == 0) ? 2ULL : 1ULL;
            unsigned long long pkt = (st << 32) | (unsigned int)xs;
            atomicExch(&g_scan_flag[b], pkt);
        }
    }
    __syncthreads();
    int block_incl = x + warp_x[wid];   // inclusive scan within block
    // windowed lookback by warp 0
    if (wid == 0) {
        int prefix = 0;
        if (b > 0) {
            int j = b - 1;
            while (true) {
                int idx = j - lane;
                unsigned long long pkt = (idx >= 0)
                    ? atomicAdd(&g_scan_flag[idx], 0ULL)
                    : (2ULL << 32);
                int st = (int)(pkt >> 32);
                unsigned rdy = __ballot_sync(0xFFFFFFFFu, st != 0);
                if (rdy != 0xFFFFFFFFu) continue;
                unsigned pm = __ballot_sync(0xFFFFFFFFu, st == 2);
                int stop = pm ? (__ffs(pm) - 1) : 32;
                int val = (lane <= stop) ? (int)(unsigned int)pkt : 0;
#pragma unroll
                for (int off = 16; off > 0; off >>= 1)
                    val += __shfl_down_sync(0xFFFFFFFFu, val, off);
                prefix += __shfl_sync(0xFFFFFFFFu, val, 0);
                if (stop < 32) break;
                j -= 32;
            }
        }
        if (lane == 0) s_prefix = prefix;
    }
    __syncthreads();
    int prefix = s_prefix;
    if (t == SCAN_B - 1) {
        unsigned long long pkt = (2ULL << 32) | (unsigned int)(prefix + block_incl);
        atomicExch(&g_scan_flag[b], pkt);
    }
    int excl = prefix + block_incl - v;
    if (i < N_NODES) {
        g_row_ptr[i] = excl;
        g_cur[i] = excl;
    }
    if (i == N_NODES) g_row_ptr[N_NODES] = E;
}

// ---------------- CSR fill (src only; no norms) --------------------------------
__global__ void fill_csr_kernel(const int* __restrict__ ei, int E) {
    int e = blockIdx.x * blockDim.x + threadIdx.x;
    if (e >= E) return;
    int s = load_idx(ei, e);
    int d = load_idx(ei, (long long)E + e);
    int pos = atomicAdd(&g_cur[d], 1);
    g_csr_i[pos] = s;
}

// ---------------- layer 1: gather(p_hat) + scale + GEMM 3->64 + ReLU + scale --
// writes h1_hat = dinv * relu(agg @ W1 + b1)
__global__ void __launch_bounds__(128)
layer1_kernel(const float* __restrict__ W1, const float* __restrict__ b1,
              float* __restrict__ h1) {
    __shared__ float sW[3 * 64];
    __shared__ float sb[64];
    for (int i = threadIdx.x; i < 3 * 64; i += 128) sW[i] = W1[i];
    if (threadIdx.x < 64) sb[threadIdx.x] = b1[threadIdx.x];
    __syncthreads();
    int v = blockIdx.x * 128 + threadIdx.x;
    if (v >= N_NODES) return;
    float4 pv = g_pos4[v];            // already dinv-scaled
    float a0 = pv.x, a1 = pv.y, a2 = pv.z;
    int e = g_row_ptr[v], end = g_row_ptr[v + 1];
    for (; e + 2 <= end; e += 2) {
        int s0 = g_csr_i[e], s1 = g_csr_i[e + 1];
        float4 f0 = g_pos4[s0];
        float4 f1 = g_pos4[s1];
        a0 += f0.x + f1.x;
        a1 += f0.y + f1.y;
        a2 += f0.z + f1.z;
    }
    if (e < end) {
        float4 f = g_pos4[g_csr_i[e]];
        a0 += f.x; a1 += f.y; a2 += f.z;
    }
    float di = g_dinv[v];
    a0 *= di; a1 *= di; a2 *= di;     // agg = dinv * (self + sum)
    float* o = h1 + (long long)v * 64;
#pragma unroll
    for (int j4 = 0; j4 < 16; j4++) {
        float4 r;
        float* rr = (float*)&r;
#pragma unroll
        for (int u = 0; u < 4; u++) {
            int j = j4 * 4 + u;
            float acc = sb[j];
            acc = fmaf(a0, sW[j], acc);
            acc = fmaf(a1, sW[64 + j], acc);
            acc = fmaf(a2, sW[128 + j], acc);
            rr[u] = di * fmaxf(acc, 0.0f);   // store scaled activation
        }
        *(float4*)(o + j4 * 4) = r;
    }
}

// ---------------- layer 2+3: gather(h1_hat) + GEMM64x64 + ReLU + GEMM64x24 -----
// Half-warp per node: lane owns a float4 of features (16 lanes x 4 = 64).
// Stores y_hat = dinv * (h2 @ W3)  [follows from scaled tile by linearity]
#define L2_NPB 64   // nodes per block: 8 warps x 2 nodes x 4 iterations
__global__ void __launch_bounds__(256)
layer2_kernel(const float* __restrict__ h1, const float* __restrict__ W2,
              const float* __restrict__ b2, const float* __restrict__ W3,
              float* __restrict__ y) {
    __shared__ float sW2[64 * 64];
    __shared__ float sW3[64 * 24];
    __shared__ float sb2[64];
    __shared__ float tile[16][64];
    int t = threadIdx.x;
    for (int i = t; i < 64 * 64; i += 256) sW2[i] = W2[i];
    for (int i = t; i < 64 * 24; i += 256) sW3[i] = W3[i];
    if (t < 64) sb2[t] = b2[t];
    __syncthreads();
    int warp = t >> 5, lane = t & 31;
    int half = lane >> 4, q = lane & 15;
#pragma unroll
    for (int it = 0; it < L2_NPB / 16; it++) {
        int vbase = blockIdx.x * L2_NPB + it * 16 + warp * 2;
        int v = vbase + half;
        // ---- gather phase (pure adds; norms factored out) ----
        float4 a = make_float4(0.0f, 0.0f, 0.0f, 0.0f);
        float di = 0.0f;
        if (v < N_NODES) {
            di = g_dinv[v];
            a = ((const float4*)(h1 + (long long)v * 64))[q];   // self (scaled)
            int e = g_row_ptr[v], end = g_row_ptr[v + 1];
            for (; e + 2 <= end; e += 2) {
                int s0 = g_csr_i[e], s1 = g_csr_i[e + 1];
                float4 f0 = ((const float4*)(h1 + (long long)s0 * 64))[q];
                float4 f1 = ((const float4*)(h1 + (long long)s1 * 64))[q];
                a.x += f0.x + f1.x;
                a.y += f0.y + f1.y;
                a.z += f0.z + f1.z;
                a.w += f0.w + f1.w;
            }
            if (e < end) {
                float4 f = ((const float4*)(h1 + (long long)g_csr_i[e] * 64))[q];
                a.x += f.x; a.y += f.y; a.z += f.z; a.w += f.w;
            }
            a.x *= di; a.y *= di; a.z *= di; a.w *= di;   // agg = dinv*(self+sum)
        }
        ((float4*)tile[warp * 2 + half])[q] = a;
        __syncwarp();
        // ---- GEMM phase: warp handles its 2 nodes sequentially ----
#pragma unroll
        for (int s = 0; s < 2; s++) {
            int vv = vbase + s;
            if (vv >= N_NODES) continue;
            float dvv = g_dinv[vv];
            float* row = tile[warp * 2 + s];
            float c0 = sb2[lane], c1 = sb2[lane + 32];
#pragma unroll
            for (int k = 0; k < 64; k++) {
                float xk = row[k];
                c0 = fmaf(xk, sW2[k * 64 + lane], c0);
                c1 = fmaf(xk, sW2[k * 64 + lane + 32], c1);
            }
            c0 = dvv * fmaxf(c0, 0.0f);   // h2_hat = dinv * relu(...)
            c1 = dvv * fmaxf(c1, 0.0f);
            __syncwarp();
            row[lane] = c0;
            row[lane + 32] = c1;
            __syncwarp();
            if (lane < 24) {
                float acc = 0.0f;
#pragma unroll
                for (int k = 0; k < 64; k++)
                    acc = fmaf(row[k], sW3[k * 24 + lane], acc);
                y[(long long)vv * 32 + lane] = acc;   // = y_hat (scaled by linearity)
            }
            __syncwarp();
        }
    }
}

// ---------------- layer 3 aggregate (dim 24, stride 32) + fused pooling -------
__global__ void __launch_bounds__(256)
gather24_pool_kernel(const float* __restrict__ y) {
    int gtid = blockIdx.x * blockDim.x + threadIdx.x;
    int v = gtid >> 5;
    int lane = gtid & 31;
    if (v >= N_NODES || lane >= 24) return;
    float a = y[(long long)v * 32 + lane];   // self (scaled)
    int e = g_row_ptr[v], end = g_row_ptr[v + 1];
    for (; e + 4 <= end; e += 4) {
        int s0 = g_csr_i[e], s1 = g_csr_i[e + 1], s2 = g_csr_i[e + 2], s3 = g_csr_i[e + 3];
        float x0 = y[(long long)s0 * 32 + lane];
        float x1 = y[(long long)s1 * 32 + lane];
        float x2 = y[(long long)s2 * 32 + lane];
        float x3 = y[(long long)s3 * 32 + lane];
        a += (x0 + x1) + (x2 + x3);
    }
    for (; e < end; e++) {
        a += y[(long long)g_csr_i[e] * 32 + lane];
    }
    a *= g_dinv[v];
    int g = g_batch[v];
    atomicAdd(&g_sums[g * 24 + lane], a);
}

// ---------------- final: mean + bias + tanh -----------------------------------
__global__ void final_kernel(const float* __restrict__ b3, float* __restrict__ out) {
    int i = blockIdx.x * blockDim.x + threadIdx.x;
    if (i >= N_GRAPHS * 24) return;
    int g = i / 24;
    int j = i % 24;
    float c = g_cnt[g];
    float m = (c > 0.0f) ? (g_sums[i] / c + b3[j]) : 0.0f;
    out[i] = tanhf(m);
}

// ---------------- launch -----------------------------------------------------
extern "C" void kernel_launch(void* const* d_in, const int* in_sizes, int n_in,
                              void* d_out, int out_size) {
    const float* pos   = (const float*)d_in[0];
    const int*   ei    = (const int*)d_in[1];   // int32 or int64 (detected)
    const int*   batch = (const int*)d_in[2];
    const float* W1    = (const float*)d_in[3];
    const float* b1    = (const float*)d_in[4];
    const float* W2    = (const float*)d_in[5];
    const float* b2    = (const float*)d_in[6];
    const float* W3    = (const float*)d_in[7];
    const float* b3    = (const float*)d_in[8];
    float*       out   = (float*)d_out;

    const int E = in_sizes[1] / 2;

    float* h1; cudaGetSymbolAddress((void**)&h1, g_h);
    float* y;  cudaGetSymbolAddress((void**)&y, g_y);

    const int TB = 256;
    auto grid = [&](long long n, int tb) { return (int)((n + tb - 1) / tb); };

    detect_zero_kernel<<<grid(N_NODES, TB), TB>>>(ei, E < 2048 ? E : 2048);   // #1
    prep_kernel<<<grid(E, TB), TB>>>(ei, batch, pos, E);                      // #2
    scan_kernel<<<N_SCANB, SCAN_B>>>(E);                                      // #3
    fill_csr_kernel<<<grid(E, TB), TB>>>(ei, E);                              // #4 (profiled)
    layer1_kernel<<<grid(N_NODES, 128), 128>>>(W1, b1, h1);                   // #5
    layer2_kernel<<<grid(N_NODES, L2_NPB), 256>>>(h1, W2, b2, W3, y);         // #6
    gather24_pool_kernel<<<grid((long long)N_NODES * 32, TB), TB>>>(y);       // #7
    final_kernel<<<grid(N_GRAPHS * 24, TB), TB>>>(b3, out);                   // #8
}

// round 9
// speedup vs baseline: 1.2187x; 1.0660x over previous
#include <cuda_runtime.h>
#include <cuda_bf16.h>
#include <cstdint>

#define N_NODES 100000
#define N_GRAPHS 64
#define MAX_E    1600000
#define SCAN_B   1024
#define N_SCANB  ((N_NODES + SCAN_B - 1) / SCAN_B)   // 98

typedef unsigned long long u64;

// ---------------- f32x2 packed math (Blackwell) ------------------------------
__device__ __forceinline__ u64 pack2(float lo, float hi) {
    u64 r;
    asm("mov.b64 %0, {%1, %2};" : "=l"(r) : "f"(lo), "f"(hi));
    return r;
}
__device__ __forceinline__ void unpack2(u64 v, float& lo, float& hi) {
    asm("mov.b64 {%0, %1}, %2;" : "=f"(lo), "=f"(hi) : "l"(v));
}
__device__ __forceinline__ u64 fma2(u64 a, u64 b, u64 c) {
    u64 d;
    asm("fma.rn.f32x2 %0, %1, %2, %3;" : "=l"(d) : "l"(a), "l"(b), "l"(c));
    return d;
}

// ---------------- scratch (device globals; no allocation allowed) ----------
__device__ int   g_flag64;               // 1 if index buffers are int64
__device__ int   g_batch[N_NODES];
__device__ int   g_indeg[N_NODES];       // zeroed by layer1 tail (self-cleaning)
__device__ float g_dinv[N_NODES];
__device__ int   g_row_ptr[N_NODES + 1];
__device__ int   g_cur[N_NODES];
__device__ u64   g_scan_flag[N_SCANB];   // hi32: status(1=agg,2=pref), lo32: value
__device__ int   g_csr_i[MAX_E];         // src indices only (norms factored out)
__device__ __align__(16) float4 g_pos4[N_NODES];      // dinv-scaled pos (built in scan)
__device__ __align__(16) float  g_h[N_NODES * 64];    // scaled h1 activations
__device__ __align__(16) float  g_y[N_NODES * 32];    // scaled layer-3 pre-agg (stride 32)
__device__ float g_sums[N_GRAPHS * 24];
__device__ float g_cnt[N_GRAPHS];

// ---------------- detect dtype + zero pool/scan-state (1 block) --------------
// int64 indices (< 2^31) => every odd 32-bit word is zero. 2048 samples.
__global__ void detect_kernel(const int* __restrict__ buf, int samples) {
    __shared__ int s_nz[256];
    int t = threadIdx.x;
    int nz = 0;
    for (int i = t; i < samples; i += 256) nz |= buf[2 * i + 1];
    s_nz[t] = nz;
    __syncthreads();
    for (int off = 128; off > 0; off >>= 1) {
        if (t < off) s_nz[t] |= s_nz[t + off];
        __syncthreads();
    }
    if (t == 0) g_flag64 = (s_nz[0] == 0) ? 1 : 0;
    for (int i = t; i < N_GRAPHS * 24; i += 256) g_sums[i] = 0.0f;
    if (t < N_GRAPHS) g_cnt[t] = 0.0f;
    if (t < N_SCANB) g_scan_flag[t] = 0ULL;
}

__device__ __forceinline__ int load_idx(const int* __restrict__ buf, long long i) {
    return g_flag64 ? buf[2 * i] : buf[(int)i];
}

// ---------------- prep: batch convert + graph counts + degree ----------------
__global__ void prep_kernel(const int* __restrict__ ei, const int* __restrict__ batch, int E) {
    __shared__ float scnt[N_GRAPHS];
    int t = threadIdx.x;
    int i = blockIdx.x * blockDim.x + t;
    bool node_block = (blockIdx.x * blockDim.x) < N_NODES;   // uniform per block
    if (node_block) {
        if (t < N_GRAPHS) scnt[t] = 0.0f;
        __syncthreads();
    }
    if (i < N_NODES) {
        int g = load_idx(batch, i);
        g_batch[i] = g;
        atomicAdd(&scnt[g], 1.0f);
    }
    if (i < E) {
        int d = load_idx(ei, (long long)E + i);
        atomicAdd(&g_indeg[d], 1);
    }
    if (node_block) {
        __syncthreads();
        if (t < N_GRAPHS && scnt[t] != 0.0f) atomicAdd(&g_cnt[t], scnt[t]);
    }
}

// ---------------- single-pass scan + dinv + scaled pos4 ----------------------
// Decoupled lookback, 98 blocks (all co-resident).
__global__ void __launch_bounds__(SCAN_B)
scan_kernel(const float* __restrict__ pos, int E) {
    __shared__ int warp_x[32];
    __shared__ int s_prefix;
    int t = threadIdx.x, b = blockIdx.x;
    int lane = t & 31, wid = t >> 5;
    int i = b * SCAN_B + t;
    int v = (i < N_NODES) ? g_indeg[i] : 0;
    if (i < N_NODES) {
        float di = rsqrtf((float)(v + 1));   // +1 self-loop
        g_dinv[i] = di;
        g_pos4[i] = make_float4(di * pos[3 * i], di * pos[3 * i + 1],
                                di * pos[3 * i + 2], 0.0f);
    }
    // warp inclusive scan
    int x = v;
#pragma unroll
    for (int off = 1; off < 32; off <<= 1) {
        int y = __shfl_up_sync(0xFFFFFFFFu, x, off);
        if (lane >= off) x += y;
    }
    if (lane == 31) warp_x[wid] = x;
    __syncthreads();
    if (wid == 0) {
        int w = warp_x[lane];
        int xs = w;
#pragma unroll
        for (int off = 1; off < 32; off <<= 1) {
            int y = __shfl_up_sync(0xFFFFFFFFu, xs, off);
            if (lane >= off) xs += y;
        }
        warp_x[lane] = xs - w;   // exclusive warp offsets
        if (lane == 31) {
            u64 st = (b == 0) ? 2ULL : 1ULL;
            atomicExch(&g_scan_flag[b], (st << 32) | (unsigned int)xs);
        }
    }
    __syncthreads();
    int block_incl = x + warp_x[wid];
    if (wid == 0) {
        int prefix = 0;
        if (b > 0) {
            int j = b - 1;
            while (true) {
                int idx = j - lane;
                u64 pkt = (idx >= 0) ? atomicAdd(&g_scan_flag[idx], 0ULL) : (2ULL << 32);
                int st = (int)(pkt >> 32);
                unsigned rdy = __ballot_sync(0xFFFFFFFFu, st != 0);
                if (rdy != 0xFFFFFFFFu) continue;
                unsigned pm = __ballot_sync(0xFFFFFFFFu, st == 2);
                int stop = pm ? (__ffs(pm) - 1) : 32;
                int val = (lane <= stop) ? (int)(unsigned int)pkt : 0;
#pragma unroll
                for (int off = 16; off > 0; off >>= 1)
                    val += __shfl_down_sync(0xFFFFFFFFu, val, off);
                prefix += __shfl_sync(0xFFFFFFFFu, val, 0);
                if (stop < 32) break;
                j -= 32;
            }
        }
        if (lane == 0) s_prefix = prefix;
    }
    __syncthreads();
    int prefix = s_prefix;
    if (t == SCAN_B - 1)
        atomicExch(&g_scan_flag[b], (2ULL << 32) | (unsigned int)(prefix + block_incl));
    int excl = prefix + block_incl - v;
    if (i < N_NODES) {
        g_row_ptr[i] = excl;
        g_cur[i] = excl;
    }
    if (i == N_NODES) g_row_ptr[N_NODES] = E;
}

// ---------------- CSR fill (src only) -----------------------------------------
__global__ void fill_csr_kernel(const int* __restrict__ ei, int E) {
    int e = blockIdx.x * blockDim.x + threadIdx.x;
    if (e >= E) return;
    int s = load_idx(ei, e);
    int d = load_idx(ei, (long long)E + e);
    int pos = atomicAdd(&g_cur[d], 1);
    g_csr_i[pos] = s;
}

// ---------------- layer 1: gather(p_hat) + GEMM 3->64 (f32x2) + ReLU + scale --
__global__ void __launch_bounds__(128)
layer1_kernel(const float* __restrict__ W1, const float* __restrict__ b1,
              float* __restrict__ h1) {
    __shared__ __align__(16) float sW[3 * 64];
    __shared__ __align__(16) float sb[64];
    for (int i = threadIdx.x; i < 3 * 64; i += 128) sW[i] = W1[i];
    if (threadIdx.x < 64) sb[threadIdx.x] = b1[threadIdx.x];
    __syncthreads();
    int v = blockIdx.x * 128 + threadIdx.x;
    if (v >= N_NODES) return;
    g_indeg[v] = 0;   // self-clean for next call's prep
    float4 pv = g_pos4[v];            // already dinv-scaled
    float a0 = pv.x, a1 = pv.y, a2 = pv.z;
    int e = g_row_ptr[v], end = g_row_ptr[v + 1];
    for (; e + 2 <= end; e += 2) {
        int s0 = g_csr_i[e], s1 = g_csr_i[e + 1];
        float4 f0 = g_pos4[s0];
        float4 f1 = g_pos4[s1];
        a0 += f0.x + f1.x;
        a1 += f0.y + f1.y;
        a2 += f0.z + f1.z;
    }
    if (e < end) {
        float4 f = g_pos4[g_csr_i[e]];
        a0 += f.x; a1 += f.y; a2 += f.z;
    }
    float di = g_dinv[v];
    a0 *= di; a1 *= di; a2 *= di;
    u64 xx0 = pack2(a0, a0), xx1 = pack2(a1, a1), xx2 = pack2(a2, a2);
    const u64* w0 = (const u64*)sW;
    const u64* w1 = (const u64*)(sW + 64);
    const u64* w2 = (const u64*)(sW + 128);
    const u64* bb = (const u64*)sb;
    float2* o = (float2*)(h1 + (long long)v * 64);
#pragma unroll
    for (int j2 = 0; j2 < 32; j2++) {
        u64 c = bb[j2];
        c = fma2(xx0, w0[j2], c);
        c = fma2(xx1, w1[j2], c);
        c = fma2(xx2, w2[j2], c);
        float lo, hi;
        unpack2(c, lo, hi);
        o[j2] = make_float2(di * fmaxf(lo, 0.0f), di * fmaxf(hi, 0.0f));
    }
}

// ---------------- layer 2+3: gather + GEMM64x64 + ReLU + GEMM64x24 (f32x2) ----
#define L2_NPB 64   // nodes per block: 8 warps x 2 nodes x 4 iterations
__global__ void __launch_bounds__(256)
layer2_kernel(const float* __restrict__ h1, const float* __restrict__ W2,
              const float* __restrict__ b2, const float* __restrict__ W3,
              float* __restrict__ y) {
    __shared__ __align__(16) float sW2[64 * 64];
    __shared__ __align__(16) float sW3[64 * 24];
    __shared__ __align__(16) float sb2[64];
    __shared__ __align__(16) float tile[16][64];
    int t = threadIdx.x;
    for (int i = t; i < 64 * 64; i += 256) sW2[i] = W2[i];
    for (int i = t; i < 64 * 24; i += 256) sW3[i] = W3[i];
    if (t < 64) sb2[t] = b2[t];
    __syncthreads();
    int warp = t >> 5, lane = t & 31;
    int half = lane >> 4, q = lane & 15;
    const u64* w2p = (const u64*)sW2;   // 32 u64 per k-row
    const u64* w3p = (const u64*)sW3;   // 12 u64 per k-row
#pragma unroll
    for (int it = 0; it < L2_NPB / 16; it++) {
        int vbase = blockIdx.x * L2_NPB + it * 16 + warp * 2;
        int v = vbase + half;
        // ---- gather phase (half-warp per node, float4 per lane, pure adds) ----
        float4 a = make_float4(0.0f, 0.0f, 0.0f, 0.0f);
        if (v < N_NODES) {
            float di = g_dinv[v];
            a = ((const float4*)(h1 + (long long)v * 64))[q];
            int e = g_row_ptr[v], end = g_row_ptr[v + 1];
            for (; e + 2 <= end; e += 2) {
                int s0 = g_csr_i[e], s1 = g_csr_i[e + 1];
                float4 f0 = ((const float4*)(h1 + (long long)s0 * 64))[q];
                float4 f1 = ((const float4*)(h1 + (long long)s1 * 64))[q];
                a.x += f0.x + f1.x;
                a.y += f0.y + f1.y;
                a.z += f0.z + f1.z;
                a.w += f0.w + f1.w;
            }
            if (e < end) {
                float4 f = ((const float4*)(h1 + (long long)g_csr_i[e] * 64))[q];
                a.x += f.x; a.y += f.y; a.z += f.z; a.w += f.w;
            }
            a.x *= di; a.y *= di; a.z *= di; a.w *= di;
        }
        ((float4*)tile[warp * 2 + half])[q] = a;
        __syncwarp();
        // ---- GEMM phase: warp handles its 2 nodes; lane owns outputs (2l,2l+1) ----
#pragma unroll
        for (int s = 0; s < 2; s++) {
            int vv = vbase + s;
            if (vv >= N_NODES) continue;
            float dvv = g_dinv[vv];
            float* row = tile[warp * 2 + s];
            u64 c01 = ((const u64*)sb2)[lane];
#pragma unroll
            for (int k4 = 0; k4 < 16; k4++) {
                float4 xv = ((const float4*)row)[k4];
                float xs[4] = {xv.x, xv.y, xv.z, xv.w};
#pragma unroll
                for (int kk = 0; kk < 4; kk++) {
                    u64 xx = pack2(xs[kk], xs[kk]);
                    c01 = fma2(xx, w2p[(k4 * 4 + kk) * 32 + lane], c01);
                }
            }
            float c0, c1;
            unpack2(c01, c0, c1);
            c0 = dvv * fmaxf(c0, 0.0f);
            c1 = dvv * fmaxf(c1, 0.0f);
            __syncwarp();
            ((float2*)row)[lane] = make_float2(c0, c1);   // row[2l], row[2l+1]
            __syncwarp();
            if (lane < 12) {
                u64 acc = 0ULL;   // two packed +0.0f
#pragma unroll
                for (int k4 = 0; k4 < 16; k4++) {
                    float4 xv = ((const float4*)row)[k4];
                    float xs[4] = {xv.x, xv.y, xv.z, xv.w};
#pragma unroll
                    for (int kk = 0; kk < 4; kk++) {
                        u64 xx = pack2(xs[kk], xs[kk]);
                        acc = fma2(xx, w3p[(k4 * 4 + kk) * 12 + lane], acc);
                    }
                }
                float y0, y1;
                unpack2(acc, y0, y1);
                ((float2*)(y + (long long)vv * 32))[lane] = make_float2(y0, y1);
            }
            __syncwarp();
        }
    }
}

// ---------------- layer 3 aggregate + pooling (register-carry over sorted batch)
// Warp walks 8 consecutive nodes; lanes 0-11 own float2 feature pairs.
__global__ void __launch_bounds__(256)
gather24_pool_kernel(const float* __restrict__ y) {
    int gwarp = (blockIdx.x * 256 + threadIdx.x) >> 5;
    int lane = threadIdx.x & 31;
    int vbeg = gwarp * 8;
    if (vbeg >= N_NODES || lane >= 12) return;
    float2 acc = make_float2(0.0f, 0.0f);
    int curg = -1;
#pragma unroll 1
    for (int u = 0; u < 8; u++) {
        int v = vbeg + u;
        if (v >= N_NODES) break;
        float2 a = ((const float2*)(y + (long long)v * 32))[lane];
        int e = g_row_ptr[v], end = g_row_ptr[v + 1];
        for (; e + 2 <= end; e += 2) {
            int s0 = g_csr_i[e], s1 = g_csr_i[e + 1];
            float2 f0 = ((const float2*)(y + (long long)s0 * 32))[lane];
            float2 f1 = ((const float2*)(y + (long long)s1 * 32))[lane];
            a.x += f0.x + f1.x;
            a.y += f0.y + f1.y;
        }
        if (e < end) {
            float2 f = ((const float2*)(y + (long long)g_csr_i[e] * 32))[lane];
            a.x += f.x; a.y += f.y;
        }
        float dv = g_dinv[v];
        a.x *= dv; a.y *= dv;
        int g = g_batch[v];
        if (g != curg) {
            if (curg >= 0) {
                atomicAdd(&g_sums[curg * 24 + 2 * lane], acc.x);
                atomicAdd(&g_sums[curg * 24 + 2 * lane + 1], acc.y);
            }
            curg = g;
            acc = a;
        } else {
            acc.x += a.x;
            acc.y += a.y;
        }
    }
    if (curg >= 0) {
        atomicAdd(&g_sums[curg * 24 + 2 * lane], acc.x);
        atomicAdd(&g_sums[curg * 24 + 2 * lane + 1], acc.y);
    }
}

// ---------------- final: mean + bias + tanh -----------------------------------
__global__ void final_kernel(const float* __restrict__ b3, float* __restrict__ out) {
    int i = blockIdx.x * blockDim.x + threadIdx.x;
    if (i >= N_GRAPHS * 24) return;
    int g = i / 24;
    int j = i % 24;
    float c = g_cnt[g];
    float m = (c > 0.0f) ? (g_sums[i] / c + b3[j]) : 0.0f;
    out[i] = tanhf(m);
}

// ---------------- launch -----------------------------------------------------
extern "C" void kernel_launch(void* const* d_in, const int* in_sizes, int n_in,
                              void* d_out, int out_size) {
    const float* pos   = (const float*)d_in[0];
    const int*   ei    = (const int*)d_in[1];   // int32 or int64 (detected)
    const int*   batch = (const int*)d_in[2];
    const float* W1    = (const float*)d_in[3];
    const float* b1    = (const float*)d_in[4];
    const float* W2    = (const float*)d_in[5];
    const float* b2    = (const float*)d_in[6];
    const float* W3    = (const float*)d_in[7];
    const float* b3    = (const float*)d_in[8];
    float*       out   = (float*)d_out;

    const int E = in_sizes[1] / 2;

    float* h1; cudaGetSymbolAddress((void**)&h1, g_h);
    float* y;  cudaGetSymbolAddress((void**)&y, g_y);

    const int TB = 256;
    auto grid = [&](long long n, int tb) { return (int)((n + tb - 1) / tb); };

    detect_kernel<<<1, 256>>>(ei, E < 2048 ? E : 2048);                       // #1
    prep_kernel<<<grid(E, TB), TB>>>(ei, batch, E);                           // #2
    scan_kernel<<<N_SCANB, SCAN_B>>>(pos, E);                                 // #3
    fill_csr_kernel<<<grid(E, TB), TB>>>(ei, E);                              // #4 (profiled)
    layer1_kernel<<<grid(N_NODES, 128), 128>>>(W1, b1, h1);                   // #5
    layer2_kernel<<<grid(N_NODES, L2_NPB), 256>>>(h1, W2, b2, W3, y);         // #6
    gather24_pool_kernel<<<grid((long long)N_NODES * 4, TB), TB>>>(y);        // #7
    final_kernel<<<grid(N_GRAPHS * 24, TB), TB>>>(b3, out);                   // #8
}

// round 10
// speedup vs baseline: 1.2516x; 1.0270x over previous
#include <cuda_runtime.h>
#include <cuda_fp16.h>
#include <cstdint>

#define N_NODES 100000
#define N_GRAPHS 64
#define MAX_E    1600000
#define SCAN_B   1024
#define N_SCANB  ((N_NODES + SCAN_B - 1) / SCAN_B)   // 98

typedef unsigned long long u64;

// ---------------- f32x2 packed math (Blackwell) ------------------------------
__device__ __forceinline__ u64 pack2(float lo, float hi) {
    u64 r;
    asm("mov.b64 %0, {%1, %2};" : "=l"(r) : "f"(lo), "f"(hi));
    return r;
}
__device__ __forceinline__ void unpack2(u64 v, float& lo, float& hi) {
    asm("mov.b64 {%0, %1}, %2;" : "=f"(lo), "=f"(hi) : "l"(v));
}
__device__ __forceinline__ u64 fma2(u64 a, u64 b, u64 c) {
    u64 d;
    asm("fma.rn.f32x2 %0, %1, %2, %3;" : "=l"(d) : "l"(a), "l"(b), "l"(c));
    return d;
}

// ---------------- scratch (device globals; no allocation allowed) ----------
__device__ int   g_flag64;               // 1 if index buffers are int64
__device__ int   g_batch[N_NODES];
__device__ int   g_indeg[N_NODES];       // zeroed by layer1 tail (self-cleaning)
__device__ float g_dinv[N_NODES];
__device__ int   g_row_ptr[N_NODES + 1];
__device__ int   g_cur[N_NODES];
__device__ u64   g_scan_flag[N_SCANB];   // hi32: status(1=agg,2=pref), lo32: value
__device__ int   g_csr_i[MAX_E];         // src indices only (norms factored out)
__device__ __align__(16) float4 g_pos4[N_NODES];        // dinv-scaled pos (built in scan)
__device__ __align__(16) __half g_h16[N_NODES * 64];    // scaled h1 activations (fp16)
__device__ __align__(16) __half g_y16[N_NODES * 32];    // scaled layer-3 pre-agg (fp16, stride 32, 24 used)
__device__ float g_sums[N_GRAPHS * 24];
__device__ float g_cnt[N_GRAPHS];

// ---------------- detect dtype + zero pool/scan-state (1 block) --------------
// int64 indices (< 2^31) => every odd 32-bit word is zero. 2048 samples.
__global__ void detect_kernel(const int* __restrict__ buf, int samples) {
    __shared__ int s_nz[256];
    int t = threadIdx.x;
    int nz = 0;
    for (int i = t; i < samples; i += 256) nz |= buf[2 * i + 1];
    s_nz[t] = nz;
    __syncthreads();
    for (int off = 128; off > 0; off >>= 1) {
        if (t < off) s_nz[t] |= s_nz[t + off];
        __syncthreads();
    }
    if (t == 0) g_flag64 = (s_nz[0] == 0) ? 1 : 0;
    for (int i = t; i < N_GRAPHS * 24; i += 256) g_sums[i] = 0.0f;
    if (t < N_GRAPHS) g_cnt[t] = 0.0f;
    if (t < N_SCANB) g_scan_flag[t] = 0ULL;
}

__device__ __forceinline__ int load_idx(const int* __restrict__ buf, long long i) {
    return g_flag64 ? buf[2 * i] : buf[(int)i];
}

// ---------------- prep: batch convert + graph counts + degree ----------------
__global__ void prep_kernel(const int* __restrict__ ei, const int* __restrict__ batch, int E) {
    __shared__ float scnt[N_GRAPHS];
    int t = threadIdx.x;
    int i = blockIdx.x * blockDim.x + t;
    bool node_block = (blockIdx.x * blockDim.x) < N_NODES;   // uniform per block
    if (node_block) {
        if (t < N_GRAPHS) scnt[t] = 0.0f;
        __syncthreads();
    }
    if (i < N_NODES) {
        int g = load_idx(batch, i);
        g_batch[i] = g;
        atomicAdd(&scnt[g], 1.0f);
    }
    if (i < E) {
        int d = load_idx(ei, (long long)E + i);
        atomicAdd(&g_indeg[d], 1);
    }
    if (node_block) {
        __syncthreads();
        if (t < N_GRAPHS && scnt[t] != 0.0f) atomicAdd(&g_cnt[t], scnt[t]);
    }
}

// ---------------- single-pass scan + dinv + scaled pos4 ----------------------
// Decoupled lookback, 98 blocks (all co-resident).
__global__ void __launch_bounds__(SCAN_B)
scan_kernel(const float* __restrict__ pos, int E) {
    __shared__ int warp_x[32];
    __shared__ int s_prefix;
    int t = threadIdx.x, b = blockIdx.x;
    int lane = t & 31, wid = t >> 5;
    int i = b * SCAN_B + t;
    int v = (i < N_NODES) ? g_indeg[i] : 0;
    if (i < N_NODES) {
        float di = rsqrtf((float)(v + 1));   // +1 self-loop
        g_dinv[i] = di;
        g_pos4[i] = make_float4(di * pos[3 * i], di * pos[3 * i + 1],
                                di * pos[3 * i + 2], 0.0f);
    }
    // warp inclusive scan
    int x = v;
#pragma unroll
    for (int off = 1; off < 32; off <<= 1) {
        int y = __shfl_up_sync(0xFFFFFFFFu, x, off);
        if (lane >= off) x += y;
    }
    if (lane == 31) warp_x[wid] = x;
    __syncthreads();
    if (wid == 0) {
        int w = warp_x[lane];
        int xs = w;
#pragma unroll
        for (int off = 1; off < 32; off <<= 1) {
            int y = __shfl_up_sync(0xFFFFFFFFu, xs, off);
            if (lane >= off) xs += y;
        }
        warp_x[lane] = xs - w;   // exclusive warp offsets
        if (lane == 31) {
            u64 st = (b == 0) ? 2ULL : 1ULL;
            atomicExch(&g_scan_flag[b], (st << 32) | (unsigned int)xs);
        }
    }
    __syncthreads();
    int block_incl = x + warp_x[wid];
    if (wid == 0) {
        int prefix = 0;
        if (b > 0) {
            int j = b - 1;
            while (true) {
                int idx = j - lane;
                u64 pkt = (idx >= 0) ? atomicAdd(&g_scan_flag[idx], 0ULL) : (2ULL << 32);
                int st = (int)(pkt >> 32);
                unsigned rdy = __ballot_sync(0xFFFFFFFFu, st != 0);
                if (rdy != 0xFFFFFFFFu) continue;
                unsigned pm = __ballot_sync(0xFFFFFFFFu, st == 2);
                int stop = pm ? (__ffs(pm) - 1) : 32;
                int val = (lane <= stop) ? (int)(unsigned int)pkt : 0;
#pragma unroll
                for (int off = 16; off > 0; off >>= 1)
                    val += __shfl_down_sync(0xFFFFFFFFu, val, off);
                prefix += __shfl_sync(0xFFFFFFFFu, val, 0);
                if (stop < 32) break;
                j -= 32;
            }
        }
        if (lane == 0) s_prefix = prefix;
    }
    __syncthreads();
    int prefix = s_prefix;
    if (t == SCAN_B - 1)
        atomicExch(&g_scan_flag[b], (2ULL << 32) | (unsigned int)(prefix + block_incl));
    int excl = prefix + block_incl - v;
    if (i < N_NODES) {
        g_row_ptr[i] = excl;
        g_cur[i] = excl;
    }
    if (i == N_NODES) g_row_ptr[N_NODES] = E;
}

// ---------------- CSR fill (src only) -----------------------------------------
__global__ void fill_csr_kernel(const int* __restrict__ ei, int E) {
    int e = blockIdx.x * blockDim.x + threadIdx.x;
    if (e >= E) return;
    int s = load_idx(ei, e);
    int d = load_idx(ei, (long long)E + e);
    int pos = atomicAdd(&g_cur[d], 1);
    g_csr_i[pos] = s;
}

// ---------------- layer 1: gather(p_hat) + GEMM 3->64 (f32x2) + ReLU + scale --
// writes h1_hat = fp16(dinv * relu(...))
__global__ void __launch_bounds__(128)
layer1_kernel(const float* __restrict__ W1, const float* __restrict__ b1,
              __half* __restrict__ h1) {
    __shared__ __align__(16) float sW[3 * 64];
    __shared__ __align__(16) float sb[64];
    for (int i = threadIdx.x; i < 3 * 64; i += 128) sW[i] = W1[i];
    if (threadIdx.x < 64) sb[threadIdx.x] = b1[threadIdx.x];
    __syncthreads();
    int v = blockIdx.x * 128 + threadIdx.x;
    if (v >= N_NODES) return;
    g_indeg[v] = 0;   // self-clean for next call's prep
    float4 pv = g_pos4[v];            // already dinv-scaled
    float a0 = pv.x, a1 = pv.y, a2 = pv.z;
    int e = g_row_ptr[v], end = g_row_ptr[v + 1];
    for (; e + 2 <= end; e += 2) {
        int s0 = g_csr_i[e], s1 = g_csr_i[e + 1];
        float4 f0 = g_pos4[s0];
        float4 f1 = g_pos4[s1];
        a0 += f0.x + f1.x;
        a1 += f0.y + f1.y;
        a2 += f0.z + f1.z;
    }
    if (e < end) {
        float4 f = g_pos4[g_csr_i[e]];
        a0 += f.x; a1 += f.y; a2 += f.z;
    }
    float di = g_dinv[v];
    a0 *= di; a1 *= di; a2 *= di;
    u64 xx0 = pack2(a0, a0), xx1 = pack2(a1, a1), xx2 = pack2(a2, a2);
    const u64* w0 = (const u64*)sW;
    const u64* w1 = (const u64*)(sW + 64);
    const u64* w2 = (const u64*)(sW + 128);
    const u64* bb = (const u64*)sb;
    __half2* o = (__half2*)(h1 + (long long)v * 64);
#pragma unroll
    for (int j2 = 0; j2 < 32; j2++) {
        u64 c = bb[j2];
        c = fma2(xx0, w0[j2], c);
        c = fma2(xx1, w1[j2], c);
        c = fma2(xx2, w2[j2], c);
        float lo, hi;
        unpack2(c, lo, hi);
        o[j2] = __floats2half2_rn(di * fmaxf(lo, 0.0f), di * fmaxf(hi, 0.0f));
    }
}

// ---------------- layer 2+3: gather(fp16) + GEMM64x64 + ReLU + GEMM64x24 ------
#define L2_NPB 64   // nodes per block: 8 warps x 2 nodes x 4 iterations
__global__ void __launch_bounds__(256)
layer2_kernel(const __half* __restrict__ h1, const float* __restrict__ W2,
              const float* __restrict__ b2, const float* __restrict__ W3,
              __half* __restrict__ y) {
    __shared__ __align__(16) float sW2[64 * 64];
    __shared__ __align__(16) float sW3[64 * 24];
    __shared__ __align__(16) float sb2[64];
    __shared__ __align__(16) float tile[16][64];
    int t = threadIdx.x;
    for (int i = t; i < 64 * 64; i += 256) sW2[i] = W2[i];
    for (int i = t; i < 64 * 24; i += 256) sW3[i] = W3[i];
    if (t < 64) sb2[t] = b2[t];
    __syncthreads();
    int warp = t >> 5, lane = t & 31;
    int half = lane >> 4, q = lane & 15;
    const u64* w2p = (const u64*)sW2;   // 32 u64 per k-row
    const u64* w3p = (const u64*)sW3;   // 12 u64 per k-row
#pragma unroll
    for (int it = 0; it < L2_NPB / 16; it++) {
        int vbase = blockIdx.x * L2_NPB + it * 16 + warp * 2;
        int v = vbase + half;
        // ---- gather phase (half-warp per node, 4 halves per lane, fp32 accum) ----
        float4 a = make_float4(0.0f, 0.0f, 0.0f, 0.0f);
        if (v < N_NODES) {
            float di = g_dinv[v];
            {
                uint2 u = ((const uint2*)(h1 + (long long)v * 64))[q];
                float2 fa = __half22float2(*(__half2*)&u.x);
                float2 fb = __half22float2(*(__half2*)&u.y);
                a = make_float4(fa.x, fa.y, fb.x, fb.y);
            }
            int e = g_row_ptr[v], end = g_row_ptr[v + 1];
            for (; e + 2 <= end; e += 2) {
                int s0 = g_csr_i[e], s1 = g_csr_i[e + 1];
                uint2 u0 = ((const uint2*)(h1 + (long long)s0 * 64))[q];
                uint2 u1 = ((const uint2*)(h1 + (long long)s1 * 64))[q];
                float2 fa0 = __half22float2(*(__half2*)&u0.x);
                float2 fb0 = __half22float2(*(__half2*)&u0.y);
                float2 fa1 = __half22float2(*(__half2*)&u1.x);
                float2 fb1 = __half22float2(*(__half2*)&u1.y);
                a.x += fa0.x + fa1.x;
                a.y += fa0.y + fa1.y;
                a.z += fb0.x + fb1.x;
                a.w += fb0.y + fb1.y;
            }
            if (e < end) {
                uint2 u = ((const uint2*)(h1 + (long long)g_csr_i[e] * 64))[q];
                float2 fa = __half22float2(*(__half2*)&u.x);
                float2 fb = __half22float2(*(__half2*)&u.y);
                a.x += fa.x; a.y += fa.y; a.z += fb.x; a.w += fb.y;
            }
            a.x *= di; a.y *= di; a.z *= di; a.w *= di;
        }
        ((float4*)tile[warp * 2 + half])[q] = a;
        __syncwarp();
        // ---- GEMM phase: warp handles its 2 nodes; lane owns outputs (2l,2l+1) ----
#pragma unroll
        for (int s = 0; s < 2; s++) {
            int vv = vbase + s;
            if (vv >= N_NODES) continue;
            float dvv = g_dinv[vv];
            float* row = tile[warp * 2 + s];
            u64 c01 = ((const u64*)sb2)[lane];
#pragma unroll
            for (int k4 = 0; k4 < 16; k4++) {
                float4 xv = ((const float4*)row)[k4];
                float xs[4] = {xv.x, xv.y, xv.z, xv.w};
#pragma unroll
                for (int kk = 0; kk < 4; kk++) {
                    u64 xx = pack2(xs[kk], xs[kk]);
                    c01 = fma2(xx, w2p[(k4 * 4 + kk) * 32 + lane], c01);
                }
            }
            float c0, c1;
            unpack2(c01, c0, c1);
            c0 = dvv * fmaxf(c0, 0.0f);
            c1 = dvv * fmaxf(c1, 0.0f);
            __syncwarp();
            ((float2*)row)[lane] = make_float2(c0, c1);   // row[2l], row[2l+1]
            __syncwarp();
            if (lane < 12) {
                u64 acc = 0ULL;   // two packed +0.0f
#pragma unroll
                for (int k4 = 0; k4 < 16; k4++) {
                    float4 xv = ((const float4*)row)[k4];
                    float xs[4] = {xv.x, xv.y, xv.z, xv.w};
#pragma unroll
                    for (int kk = 0; kk < 4; kk++) {
                        u64 xx = pack2(xs[kk], xs[kk]);
                        acc = fma2(xx, w3p[(k4 * 4 + kk) * 12 + lane], acc);
                    }
                }
                float y0, y1;
                unpack2(acc, y0, y1);
                ((__half2*)(y + (long long)vv * 32))[lane] = __floats2half2_rn(y0, y1);
            }
            __syncwarp();
        }
    }
}

// ---------------- layer 3 aggregate + pooling (register-carry over sorted batch)
// Warp walks 8 consecutive nodes; lanes 0-11 own half2 feature pairs.
__global__ void __launch_bounds__(256)
gather24_pool_kernel(const __half* __restrict__ y) {
    int gwarp = (blockIdx.x * 256 + threadIdx.x) >> 5;
    int lane = threadIdx.x & 31;
    int vbeg = gwarp * 8;
    if (vbeg >= N_NODES || lane >= 12) return;
    float2 acc = make_float2(0.0f, 0.0f);
    int curg = -1;
#pragma unroll 1
    for (int u = 0; u < 8; u++) {
        int v = vbeg + u;
        if (v >= N_NODES) break;
        float2 a = __half22float2(((const __half2*)(y + (long long)v * 32))[lane]);
        int e = g_row_ptr[v], end = g_row_ptr[v + 1];
        for (; e + 2 <= end; e += 2) {
            int s0 = g_csr_i[e], s1 = g_csr_i[e + 1];
            float2 f0 = __half22float2(((const __half2*)(y + (long long)s0 * 32))[lane]);
            float2 f1 = __half22float2(((const __half2*)(y + (long long)s1 * 32))[lane]);
            a.x += f0.x + f1.x;
            a.y += f0.y + f1.y;
        }
        if (e < end) {
            float2 f = __half22float2(((const __half2*)(y + (long long)g_csr_i[e] * 32))[lane]);
            a.x += f.x; a.y += f.y;
        }
        float dv = g_dinv[v];
        a.x *= dv; a.y *= dv;
        int g = g_batch[v];
        if (g != curg) {
            if (curg >= 0) {
                atomicAdd(&g_sums[curg * 24 + 2 * lane], acc.x);
                atomicAdd(&g_sums[curg * 24 + 2 * lane + 1], acc.y);
            }
            curg = g;
            acc = a;
        } else {
            acc.x += a.x;
            acc.y += a.y;
        }
    }
    if (curg >= 0) {
        atomicAdd(&g_sums[curg * 24 + 2 * lane], acc.x);
        atomicAdd(&g_sums[curg * 24 + 2 * lane + 1], acc.y);
    }
}

// ---------------- final: mean + bias + tanh -----------------------------------
__global__ void final_kernel(const float* __restrict__ b3, float* __restrict__ out) {
    int i = blockIdx.x * blockDim.x + threadIdx.x;
    if (i >= N_GRAPHS * 24) return;
    int g = i / 24;
    int j = i % 24;
    float c = g_cnt[g];
    float m = (c > 0.0f) ? (g_sums[i] / c + b3[j]) : 0.0f;
    out[i] = tanhf(m);
}

// ---------------- launch -----------------------------------------------------
extern "C" void kernel_launch(void* const* d_in, const int* in_sizes, int n_in,
                              void* d_out, int out_size) {
    const float* pos   = (const float*)d_in[0];
    const int*   ei    = (const int*)d_in[1];   // int32 or int64 (detected)
    const int*   batch = (const int*)d_in[2];
    const float* W1    = (const float*)d_in[3];
    const float* b1    = (const float*)d_in[4];
    const float* W2    = (const float*)d_in[5];
    const float* b2    = (const float*)d_in[6];
    const float* W3    = (const float*)d_in[7];
    const float* b3    = (const float*)d_in[8];
    float*       out   = (float*)d_out;

    const int E = in_sizes[1] / 2;

    __half* h1; cudaGetSymbolAddress((void**)&h1, g_h16);
    __half* y;  cudaGetSymbolAddress((void**)&y, g_y16);

    const int TB = 256;
    auto grid = [&](long long n, int tb) { return (int)((n + tb - 1) / tb); };

    detect_kernel<<<1, 256>>>(ei, E < 2048 ? E : 2048);                       // #1
    prep_kernel<<<grid(E, TB), TB>>>(ei, batch, E);                           // #2
    scan_kernel<<<N_SCANB, SCAN_B>>>(pos, E);                                 // #3
    fill_csr_kernel<<<grid(E, TB), TB>>>(ei, E);                              // #4 (profiled)
    layer1_kernel<<<grid(N_NODES, 128), 128>>>(W1, b1, h1);                   // #5
    layer2_kernel<<<grid(N_NODES, L2_NPB), 256>>>(h1, W2, b2, W3, y);         // #6
    gather24_pool_kernel<<<grid((long long)N_NODES * 4, TB), TB>>>(y);        // #7
    final_kernel<<<grid(N_GRAPHS * 24, TB), TB>>>(b3, out);                   // #8
}

// round 11
// speedup vs baseline: 1.3163x; 1.0516x over previous
#include <cuda_runtime.h>
#include <cuda_fp16.h>
#include <cstdint>

#define N_NODES 100000
#define N_GRAPHS 64
#define MAX_E    1600000
#define SCAN_B   1024
#define N_SCANB  ((N_NODES + SCAN_B - 1) / SCAN_B)   // 98

typedef unsigned long long u64;

// ---------------- f32x2 packed math (Blackwell) ------------------------------
__device__ __forceinline__ u64 pack2(float lo, float hi) {
    u64 r;
    asm("mov.b64 %0, {%1, %2};" : "=l"(r) : "f"(lo), "f"(hi));
    return r;
}
__device__ __forceinline__ void unpack2(u64 v, float& lo, float& hi) {
    asm("mov.b64 {%0, %1}, %2;" : "=f"(lo), "=f"(hi) : "l"(v));
}
__device__ __forceinline__ u64 fma2(u64 a, u64 b, u64 c) {
    u64 d;
    asm("fma.rn.f32x2 %0, %1, %2, %3;" : "=l"(d) : "l"(a), "l"(b), "l"(c));
    return d;
}

// ---------------- scratch (device globals; zero-initialized) ----------------
// Self-cleaning protocol: every buffer that must be zero/initial at call start
// is reset by the END of the previous call (indeg by layer1; sums/cnt/scanflag/
// done by the fused final block). First call relies on static zero-init.
__device__ int   g_flag64;               // 1 if index buffers are int64
__device__ int   g_batch[N_NODES];
__device__ int   g_indeg[N_NODES];
__device__ float g_dinv[N_NODES];
__device__ int   g_row_ptr[N_NODES + 1];
__device__ int   g_cur[N_NODES];
__device__ u64   g_scan_flag[N_SCANB];   // hi32: status(1=agg,2=pref), lo32: value
__device__ int   g_done;                 // completion counter for fused final
__device__ int   g_csr_i[MAX_E];         // src indices only (norms factored out)
__device__ __align__(16) float4 g_pos4[N_NODES];        // dinv-scaled pos
__device__ __align__(16) __half g_h16[N_NODES * 64];    // scaled h1 activations
__device__ __align__(16) __half g_y16[N_NODES * 32];    // scaled pre-agg (stride 32)
__device__ float g_sums[N_GRAPHS * 24];
__device__ float g_cnt[N_GRAPHS];

// ---------------- prep: local dtype detect + batch + counts + degree ---------
// int64 indices (< 2^31) => every odd 32-bit word is zero. 256 samples/block,
// deterministic across blocks (same sample set). Block 0 publishes g_flag64
// for later kernels.
__global__ void prep_kernel(const int* __restrict__ ei, const int* __restrict__ batch, int E) {
    __shared__ int s_nz[256];
    __shared__ float scnt[N_GRAPHS];
    int t = threadIdx.x;
    // --- local detect ---
    s_nz[t] = ei[2 * t + 1];   // E >= 256 always here (1.6M)
    __syncthreads();
    for (int off = 128; off > 0; off >>= 1) {
        if (t < off) s_nz[t] |= s_nz[t + off];
        __syncthreads();
    }
    int flag = (s_nz[0] == 0) ? 1 : 0;
    if (blockIdx.x == 0 && t == 0) g_flag64 = flag;
    // --- node/edge work ---
    int i = blockIdx.x * blockDim.x + t;
    bool node_block = (blockIdx.x * blockDim.x) < N_NODES;
    if (node_block) {
        if (t < N_GRAPHS) scnt[t] = 0.0f;
        __syncthreads();
    }
    if (i < N_NODES) {
        int g = flag ? batch[2 * i] : batch[i];
        g_batch[i] = g;
        atomicAdd(&scnt[g], 1.0f);
    }
    if (i < E) {
        int d = flag ? ei[2 * ((long long)E + i)] : ei[E + i];
        atomicAdd(&g_indeg[d], 1);
    }
    if (node_block) {
        __syncthreads();
        if (t < N_GRAPHS && scnt[t] != 0.0f) atomicAdd(&g_cnt[t], scnt[t]);
    }
}

__device__ __forceinline__ int load_idx(const int* __restrict__ buf, long long i) {
    return g_flag64 ? buf[2 * i] : buf[(int)i];
}

// ---------------- single-pass scan + dinv + scaled pos4 ----------------------
__global__ void __launch_bounds__(SCAN_B)
scan_kernel(const float* __restrict__ pos, int E) {
    __shared__ int warp_x[32];
    __shared__ int s_prefix;
    int t = threadIdx.x, b = blockIdx.x;
    int lane = t & 31, wid = t >> 5;
    int i = b * SCAN_B + t;
    int v = (i < N_NODES) ? g_indeg[i] : 0;
    if (i < N_NODES) {
        float di = rsqrtf((float)(v + 1));   // +1 self-loop
        g_dinv[i] = di;
        g_pos4[i] = make_float4(di * pos[3 * i], di * pos[3 * i + 1],
                                di * pos[3 * i + 2], 0.0f);
    }
    int x = v;
#pragma unroll
    for (int off = 1; off < 32; off <<= 1) {
        int y = __shfl_up_sync(0xFFFFFFFFu, x, off);
        if (lane >= off) x += y;
    }
    if (lane == 31) warp_x[wid] = x;
    __syncthreads();
    if (wid == 0) {
        int w = warp_x[lane];
        int xs = w;
#pragma unroll
        for (int off = 1; off < 32; off <<= 1) {
            int y = __shfl_up_sync(0xFFFFFFFFu, xs, off);
            if (lane >= off) xs += y;
        }
        warp_x[lane] = xs - w;
        if (lane == 31) {
            u64 st = (b == 0) ? 2ULL : 1ULL;
            atomicExch(&g_scan_flag[b], (st << 32) | (unsigned int)xs);
        }
    }
    __syncthreads();
    int block_incl = x + warp_x[wid];
    if (wid == 0) {
        int prefix = 0;
        if (b > 0) {
            int j = b - 1;
            while (true) {
                int idx = j - lane;
                u64 pkt = (idx >= 0) ? atomicAdd(&g_scan_flag[idx], 0ULL) : (2ULL << 32);
                int st = (int)(pkt >> 32);
                unsigned rdy = __ballot_sync(0xFFFFFFFFu, st != 0);
                if (rdy != 0xFFFFFFFFu) continue;
                unsigned pm = __ballot_sync(0xFFFFFFFFu, st == 2);
                int stop = pm ? (__ffs(pm) - 1) : 32;
                int val = (lane <= stop) ? (int)(unsigned int)pkt : 0;
#pragma unroll
                for (int off = 16; off > 0; off >>= 1)
                    val += __shfl_down_sync(0xFFFFFFFFu, val, off);
                prefix += __shfl_sync(0xFFFFFFFFu, val, 0);
                if (stop < 32) break;
                j -= 32;
            }
        }
        if (lane == 0) s_prefix = prefix;
    }
    __syncthreads();
    int prefix = s_prefix;
    if (t == SCAN_B - 1)
        atomicExch(&g_scan_flag[b], (2ULL << 32) | (unsigned int)(prefix + block_incl));
    int excl = prefix + block_incl - v;
    if (i < N_NODES) {
        g_row_ptr[i] = excl;
        g_cur[i] = excl;
    }
    if (i == N_NODES) g_row_ptr[N_NODES] = E;
}

// ---------------- CSR fill (src only) -----------------------------------------
__global__ void fill_csr_kernel(const int* __restrict__ ei, int E) {
    int e = blockIdx.x * blockDim.x + threadIdx.x;
    if (e >= E) return;
    int s = load_idx(ei, e);
    int d = load_idx(ei, (long long)E + e);
    int pos = atomicAdd(&g_cur[d], 1);
    g_csr_i[pos] = s;
}

// ---------------- layer 1: warp-per-node gather + GEMM 3->64 (f32x2) ----------
// Lane-per-edge parallel gather; butterfly reduce; lane owns outputs (2l,2l+1).
__global__ void __launch_bounds__(256)
layer1_kernel(const float* __restrict__ W1, const float* __restrict__ b1,
              __half* __restrict__ h1) {
    __shared__ __align__(16) float sW[3 * 64];
    __shared__ __align__(16) float sb[64];
    int t = threadIdx.x;
    for (int i = t; i < 3 * 64; i += 256) sW[i] = W1[i];
    if (t < 64) sb[t] = b1[t];
    __syncthreads();
    int warp = t >> 5, lane = t & 31;
    int v = blockIdx.x * 8 + warp;
    if (v >= N_NODES) return;
    if (lane == 0) g_indeg[v] = 0;   // self-clean for next call's prep
    float a0 = 0.0f, a1 = 0.0f, a2 = 0.0f;
    int e0 = g_row_ptr[v], e1 = g_row_ptr[v + 1];
    for (int e = e0 + lane; e < e1; e += 32) {
        float4 f = g_pos4[g_csr_i[e]];
        a0 += f.x; a1 += f.y; a2 += f.z;
    }
#pragma unroll
    for (int off = 16; off > 0; off >>= 1) {
        a0 += __shfl_xor_sync(0xFFFFFFFFu, a0, off);
        a1 += __shfl_xor_sync(0xFFFFFFFFu, a1, off);
        a2 += __shfl_xor_sync(0xFFFFFFFFu, a2, off);
    }
    float4 pv = g_pos4[v];           // self (already dinv-scaled)
    a0 += pv.x; a1 += pv.y; a2 += pv.z;
    float di = g_dinv[v];
    a0 *= di; a1 *= di; a2 *= di;
    u64 xx0 = pack2(a0, a0), xx1 = pack2(a1, a1), xx2 = pack2(a2, a2);
    const u64* w0 = (const u64*)sW;
    const u64* w1 = (const u64*)(sW + 64);
    const u64* w2 = (const u64*)(sW + 128);
    u64 c = ((const u64*)sb)[lane];
    c = fma2(xx0, w0[lane], c);
    c = fma2(xx1, w1[lane], c);
    c = fma2(xx2, w2[lane], c);
    float lo, hi;
    unpack2(c, lo, hi);
    ((__half2*)(h1 + (long long)v * 64))[lane] =
        __floats2half2_rn(di * fmaxf(lo, 0.0f), di * fmaxf(hi, 0.0f));
}

// ---------------- layer 2+3: gather(fp16) + GEMM64x64 + ReLU + GEMM64x24 ------
#define L2_NPB 64   // nodes per block: 8 warps x 2 nodes x 4 iterations
__global__ void __launch_bounds__(256)
layer2_kernel(const __half* __restrict__ h1, const float* __restrict__ W2,
              const float* __restrict__ b2, const float* __restrict__ W3,
              __half* __restrict__ y) {
    __shared__ __align__(16) float sW2[64 * 64];
    __shared__ __align__(16) float sW3[64 * 24];
    __shared__ __align__(16) float sb2[64];
    __shared__ __align__(16) float tile[16][64];
    int t = threadIdx.x;
    for (int i = t; i < 64 * 64; i += 256) sW2[i] = W2[i];
    for (int i = t; i < 64 * 24; i += 256) sW3[i] = W3[i];
    if (t < 64) sb2[t] = b2[t];
    __syncthreads();
    int warp = t >> 5, lane = t & 31;
    int half = lane >> 4, q = lane & 15;
    const u64* w2p = (const u64*)sW2;   // 32 u64 per k-row
    const u64* w3p = (const u64*)sW3;   // 12 u64 per k-row
#pragma unroll
    for (int it = 0; it < L2_NPB / 16; it++) {
        int vbase = blockIdx.x * L2_NPB + it * 16 + warp * 2;
        int v = vbase + half;
        // ---- gather (half-warp per node, 4 halves per lane, fp32 accum) ----
        float4 a = make_float4(0.0f, 0.0f, 0.0f, 0.0f);
        if (v < N_NODES) {
            float di = g_dinv[v];
            {
                uint2 u = ((const uint2*)(h1 + (long long)v * 64))[q];
                float2 fa = __half22float2(*(__half2*)&u.x);
                float2 fb = __half22float2(*(__half2*)&u.y);
                a = make_float4(fa.x, fa.y, fb.x, fb.y);
            }
            int e = g_row_ptr[v], end = g_row_ptr[v + 1];
            for (; e + 2 <= end; e += 2) {
                int s0 = g_csr_i[e], s1 = g_csr_i[e + 1];
                uint2 u0 = ((const uint2*)(h1 + (long long)s0 * 64))[q];
                uint2 u1 = ((const uint2*)(h1 + (long long)s1 * 64))[q];
                float2 fa0 = __half22float2(*(__half2*)&u0.x);
                float2 fb0 = __half22float2(*(__half2*)&u0.y);
                float2 fa1 = __half22float2(*(__half2*)&u1.x);
                float2 fb1 = __half22float2(*(__half2*)&u1.y);
                a.x += fa0.x + fa1.x;
                a.y += fa0.y + fa1.y;
                a.z += fb0.x + fb1.x;
                a.w += fb0.y + fb1.y;
            }
            if (e < end) {
                uint2 u = ((const uint2*)(h1 + (long long)g_csr_i[e] * 64))[q];
                float2 fa = __half22float2(*(__half2*)&u.x);
                float2 fb = __half22float2(*(__half2*)&u.y);
                a.x += fa.x; a.y += fa.y; a.z += fb.x; a.w += fb.y;
            }
            a.x *= di; a.y *= di; a.z *= di; a.w *= di;
        }
        ((float4*)tile[warp * 2 + half])[q] = a;
        __syncwarp();
        // ---- W2 GEMM + ReLU: warp handles its 2 nodes sequentially ----
#pragma unroll
        for (int s = 0; s < 2; s++) {
            int vv = vbase + s;
            if (vv >= N_NODES) continue;
            float dvv = g_dinv[vv];
            float* row = tile[warp * 2 + s];
            u64 c01 = ((const u64*)sb2)[lane];
#pragma unroll
            for (int k4 = 0; k4 < 16; k4++) {
                float4 xv = ((const float4*)row)[k4];
                float xs[4] = {xv.x, xv.y, xv.z, xv.w};
#pragma unroll
                for (int kk = 0; kk < 4; kk++) {
                    u64 xx = pack2(xs[kk], xs[kk]);
                    c01 = fma2(xx, w2p[(k4 * 4 + kk) * 32 + lane], c01);
                }
            }
            float c0, c1;
            unpack2(c01, c0, c1);
            c0 = dvv * fmaxf(c0, 0.0f);
            c1 = dvv * fmaxf(c1, 0.0f);
            __syncwarp();
            ((float2*)row)[lane] = make_float2(c0, c1);
            __syncwarp();
        }
        // ---- W3 GEMM: both nodes concurrently (lanes 0-11 / 16-27) ----
        {
            int vv = vbase + half;
            if (vv < N_NODES && q < 12) {
                float* row = tile[warp * 2 + half];
                u64 acc = 0ULL;
#pragma unroll
                for (int k4 = 0; k4 < 16; k4++) {
                    float4 xv = ((const float4*)row)[k4];
                    float xs[4] = {xv.x, xv.y, xv.z, xv.w};
#pragma unroll
                    for (int kk = 0; kk < 4; kk++) {
                        u64 xx = pack2(xs[kk], xs[kk]);
                        acc = fma2(xx, w3p[(k4 * 4 + kk) * 12 + q], acc);
                    }
                }
                float y0, y1;
                unpack2(acc, y0, y1);
                ((__half2*)(y + (long long)vv * 32))[q] = __floats2half2_rn(y0, y1);
            }
            __syncwarp();
        }
    }
}

// ---------------- layer 3 aggregate + pooling + fused final -------------------
// Warp walks 8 consecutive nodes; two edges/iter on lane-groups 0-15 / 16-31;
// lanes l<12 of each group own half2 feature pairs; combine via shfl_xor(16).
// Last block computes the output and resets persistent state.
__global__ void __launch_bounds__(256)
gather_pool_final_kernel(const __half* __restrict__ y, const float* __restrict__ b3,
                         float* __restrict__ out, int nblocks) {
    int t = threadIdx.x;
    int warp = t >> 5, lane = t & 31;
    int grp = lane >> 4, l = lane & 15;
    bool act = l < 12;
    int vbeg = (blockIdx.x * 8 + warp) * 8;
    if (vbeg < N_NODES) {
        float2 acc = make_float2(0.0f, 0.0f);
        int curg = -1;
#pragma unroll 1
        for (int u = 0; u < 8; u++) {
            int v = vbeg + u;
            if (v >= N_NODES) break;
            float2 a = make_float2(0.0f, 0.0f);
            int e0 = g_row_ptr[v], e1 = g_row_ptr[v + 1];
            for (int e = e0 + grp; e < e1; e += 2) {
                if (act) {
                    int s = g_csr_i[e];
                    float2 f = __half22float2(((const __half2*)(y + (long long)s * 32))[l]);
                    a.x += f.x; a.y += f.y;
                }
            }
            // combine the two groups
            a.x += __shfl_xor_sync(0xFFFFFFFFu, a.x, 16);
            a.y += __shfl_xor_sync(0xFFFFFFFFu, a.y, 16);
            if (grp == 0 && act) {
                float2 sf = __half22float2(((const __half2*)(y + (long long)v * 32))[l]);
                a.x += sf.x; a.y += sf.y;
                float dv = g_dinv[v];
                a.x *= dv; a.y *= dv;
                int g = g_batch[v];
                if (g != curg) {
                    if (curg >= 0) {
                        atomicAdd(&g_sums[curg * 24 + 2 * l], acc.x);
                        atomicAdd(&g_sums[curg * 24 + 2 * l + 1], acc.y);
                    }
                    curg = g;
                    acc = a;
                } else {
                    acc.x += a.x;
                    acc.y += a.y;
                }
            }
        }
        if (grp == 0 && act && curg >= 0) {
            atomicAdd(&g_sums[curg * 24 + 2 * l], acc.x);
            atomicAdd(&g_sums[curg * 24 + 2 * l + 1], acc.y);
        }
    }
    // ---- completion counter; last block runs final + state reset ----
    __syncthreads();
    __shared__ int s_last;
    if (t == 0) {
        __threadfence();
        int old = atomicAdd(&g_done, 1);
        s_last = (old == nblocks - 1) ? 1 : 0;
    }
    __syncthreads();
    if (s_last) {
        __threadfence();
        for (int i = t; i < N_GRAPHS * 24; i += 256) {
            int g = i / 24, j = i % 24;
            float c = g_cnt[g];
            float m = (c > 0.0f) ? (g_sums[i] / c + b3[j]) : 0.0f;
            out[i] = tanhf(m);
        }
        __syncthreads();
        // reset persistent state for the next call
        for (int i = t; i < N_GRAPHS * 24; i += 256) g_sums[i] = 0.0f;
        if (t < N_GRAPHS) g_cnt[t] = 0.0f;
        if (t < N_SCANB) g_scan_flag[t] = 0ULL;
        if (t == 0) g_done = 0;
    }
}

// ---------------- launch -----------------------------------------------------
extern "C" void kernel_launch(void* const* d_in, const int* in_sizes, int n_in,
                              void* d_out, int out_size) {
    const float* pos   = (const float*)d_in[0];
    const int*   ei    = (const int*)d_in[1];   // int32 or int64 (detected)
    const int*   batch = (const int*)d_in[2];
    const float* W1    = (const float*)d_in[3];
    const float* b1    = (const float*)d_in[4];
    const float* W2    = (const float*)d_in[5];
    const float* b2    = (const float*)d_in[6];
    const float* W3    = (const float*)d_in[7];
    const float* b3    = (const float*)d_in[8];
    float*       out   = (float*)d_out;

    const int E = in_sizes[1] / 2;

    __half* h1; cudaGetSymbolAddress((void**)&h1, g_h16);
    __half* y;  cudaGetSymbolAddress((void**)&y, g_y16);

    const int TB = 256;
    auto grid = [&](long long n, int tb) { return (int)((n + tb - 1) / tb); };

    int pool_blocks = grid(N_NODES, 64);   // 8 warps/block x 8 nodes/warp

    prep_kernel<<<grid(E, TB), TB>>>(ei, batch, E);                           // #1
    scan_kernel<<<N_SCANB, SCAN_B>>>(pos, E);                                 // #2
    fill_csr_kernel<<<grid(E, TB), TB>>>(ei, E);                              // #3
    layer1_kernel<<<grid(N_NODES, 8), 256>>>(W1, b1, h1);                     // #4 (profiled)
    layer2_kernel<<<grid(N_NODES, L2_NPB), 256>>>(h1, W2, b2, W3, y);         // #5
    gather_pool_final_kernel<<<pool_blocks, 256>>>(y, b3, out, pool_blocks);  // #6
}

// round 12
// speedup vs baseline: 1.3744x; 1.0442x over previous
#include <cuda_runtime.h>
#include <cuda_fp16.h>
#include <cstdint>

#define N_NODES 100000
#define N_GRAPHS 64
#define MAX_E    1600000
#define SCAN_B   1024
#define N_SCANB  ((N_NODES + SCAN_B - 1) / SCAN_B)   // 98

typedef unsigned long long u64;

// ---------------- f32x2 packed math (Blackwell) ------------------------------
__device__ __forceinline__ u64 pack2(float lo, float hi) {
    u64 r;
    asm("mov.b64 %0, {%1, %2};" : "=l"(r) : "f"(lo), "f"(hi));
    return r;
}
__device__ __forceinline__ void unpack2(u64 v, float& lo, float& hi) {
    asm("mov.b64 {%0, %1}, %2;" : "=f"(lo), "=f"(hi) : "l"(v));
}
__device__ __forceinline__ u64 fma2(u64 a, u64 b, u64 c) {
    u64 d;
    asm("fma.rn.f32x2 %0, %1, %2, %3;" : "=l"(d) : "l"(a), "l"(b), "l"(c));
    return d;
}

// ---------------- scratch (device globals; zero-initialized) ----------------
// Self-cleaning protocol: every buffer that must be zero/initial at call start
// is reset by the END of the previous call (indeg by layer1; sums/cnt/scanflag/
// done by the fused final block). First call relies on static zero-init.
__device__ int   g_flag64;               // 1 if index buffers are int64
__device__ int   g_batch[N_NODES];
__device__ int   g_indeg[N_NODES];
__device__ float g_dinv[N_NODES];
__device__ int   g_row_ptr[N_NODES + 1];
__device__ int   g_cur[N_NODES];
__device__ u64   g_scan_flag[N_SCANB];   // hi32: status(1=agg,2=pref), lo32: value
__device__ int   g_done;                 // completion counter for fused final
__device__ __align__(16) int g_csr_i[MAX_E];            // src indices only
__device__ __align__(16) float4 g_pos4[N_NODES];        // dinv-scaled pos
__device__ __align__(16) __half g_h16[N_NODES * 64];    // scaled h1 activations
__device__ __align__(16) __half g_y16[N_NODES * 32];    // scaled pre-agg (stride 32)
__device__ float g_sums[N_GRAPHS * 24];
__device__ float g_cnt[N_GRAPHS];

// ---------------- prep: local dtype detect + batch + counts + degree ---------
// int64 indices (< 2^31) => every odd 32-bit word is zero. 256 samples/block,
// deterministic across blocks. Block 0 publishes g_flag64 for later kernels.
__global__ void prep_kernel(const int* __restrict__ ei, const int* __restrict__ batch, int E) {
    __shared__ int s_nz[256];
    __shared__ float scnt[N_GRAPHS];
    int t = threadIdx.x;
    s_nz[t] = ei[2 * t + 1];   // E >= 256 always (1.6M)
    __syncthreads();
    for (int off = 128; off > 0; off >>= 1) {
        if (t < off) s_nz[t] |= s_nz[t + off];
        __syncthreads();
    }
    int flag = (s_nz[0] == 0) ? 1 : 0;
    if (blockIdx.x == 0 && t == 0) g_flag64 = flag;
    int i = blockIdx.x * blockDim.x + t;
    bool node_block = (blockIdx.x * blockDim.x) < N_NODES;
    if (node_block) {
        if (t < N_GRAPHS) scnt[t] = 0.0f;
        __syncthreads();
    }
    if (i < N_NODES) {
        int g = flag ? batch[2 * i] : batch[i];
        g_batch[i] = g;
        atomicAdd(&scnt[g], 1.0f);
    }
    if (i < E) {
        int d = flag ? ei[2 * ((long long)E + i)] : ei[E + i];
        atomicAdd(&g_indeg[d], 1);
    }
    if (node_block) {
        __syncthreads();
        if (t < N_GRAPHS && scnt[t] != 0.0f) atomicAdd(&g_cnt[t], scnt[t]);
    }
}

__device__ __forceinline__ int load_idx(const int* __restrict__ buf, long long i) {
    return g_flag64 ? buf[2 * i] : buf[(int)i];
}

// ---------------- single-pass scan + dinv + scaled pos4 ----------------------
__global__ void __launch_bounds__(SCAN_B)
scan_kernel(const float* __restrict__ pos, int E) {
    __shared__ int warp_x[32];
    __shared__ int s_prefix;
    int t = threadIdx.x, b = blockIdx.x;
    int lane = t & 31, wid = t >> 5;
    int i = b * SCAN_B + t;
    int v = (i < N_NODES) ? g_indeg[i] : 0;
    if (i < N_NODES) {
        float di = rsqrtf((float)(v + 1));   // +1 self-loop
        g_dinv[i] = di;
        g_pos4[i] = make_float4(di * pos[3 * i], di * pos[3 * i + 1],
                                di * pos[3 * i + 2], 0.0f);
    }
    int x = v;
#pragma unroll
    for (int off = 1; off < 32; off <<= 1) {
        int y = __shfl_up_sync(0xFFFFFFFFu, x, off);
        if (lane >= off) x += y;
    }
    if (lane == 31) warp_x[wid] = x;
    __syncthreads();
    if (wid == 0) {
        int w = warp_x[lane];
        int xs = w;
#pragma unroll
        for (int off = 1; off < 32; off <<= 1) {
            int y = __shfl_up_sync(0xFFFFFFFFu, xs, off);
            if (lane >= off) xs += y;
        }
        warp_x[lane] = xs - w;
        if (lane == 31) {
            u64 st = (b == 0) ? 2ULL : 1ULL;
            atomicExch(&g_scan_flag[b], (st << 32) | (unsigned int)xs);
        }
    }
    __syncthreads();
    int block_incl = x + warp_x[wid];
    if (wid == 0) {
        int prefix = 0;
        if (b > 0) {
            int j = b - 1;
            while (true) {
                int idx = j - lane;
                u64 pkt = (idx >= 0) ? atomicAdd(&g_scan_flag[idx], 0ULL) : (2ULL << 32);
                int st = (int)(pkt >> 32);
                unsigned rdy = __ballot_sync(0xFFFFFFFFu, st != 0);
                if (rdy != 0xFFFFFFFFu) continue;
                unsigned pm = __ballot_sync(0xFFFFFFFFu, st == 2);
                int stop = pm ? (__ffs(pm) - 1) : 32;
                int val = (lane <= stop) ? (int)(unsigned int)pkt : 0;
#pragma unroll
                for (int off = 16; off > 0; off >>= 1)
                    val += __shfl_down_sync(0xFFFFFFFFu, val, off);
                prefix += __shfl_sync(0xFFFFFFFFu, val, 0);
                if (stop < 32) break;
                j -= 32;
            }
        }
        if (lane == 0) s_prefix = prefix;
    }
    __syncthreads();
    int prefix = s_prefix;
    if (t == SCAN_B - 1)
        atomicExch(&g_scan_flag[b], (2ULL << 32) | (unsigned int)(prefix + block_incl));
    int excl = prefix + block_incl - v;
    if (i < N_NODES) {
        g_row_ptr[i] = excl;
        g_cur[i] = excl;
    }
    if (i == N_NODES) g_row_ptr[N_NODES] = E;
}

// ---------------- CSR fill (src only) -----------------------------------------
__global__ void fill_csr_kernel(const int* __restrict__ ei, int E) {
    int e = blockIdx.x * blockDim.x + threadIdx.x;
    if (e >= E) return;
    int s = load_idx(ei, e);
    int d = load_idx(ei, (long long)E + e);
    int pos = atomicAdd(&g_cur[d], 1);
    g_csr_i[pos] = s;
}

// ---------------- layer 1: thread-per-node gather + GEMM 3->64 (f32x2) --------
// int4 CSR loads; packed half2 register tile; uint4 stores.
__global__ void __launch_bounds__(256)
layer1_kernel(const float* __restrict__ W1, const float* __restrict__ b1,
              __half* __restrict__ h1) {
    __shared__ __align__(16) float sW[3 * 64];
    __shared__ __align__(16) float sb[64];
    int t = threadIdx.x;
    for (int i = t; i < 3 * 64; i += 256) sW[i] = W1[i];
    if (t < 64) sb[t] = b1[t];
    __syncthreads();
    int v = blockIdx.x * 256 + t;
    if (v >= N_NODES) return;
    g_indeg[v] = 0;   // self-clean for next call's prep
    float4 pv = g_pos4[v];            // self (already dinv-scaled)
    float a0 = pv.x, a1 = pv.y, a2 = pv.z;
    int e = g_row_ptr[v], end = g_row_ptr[v + 1];
    for (; e < end && (e & 3); e++) {   // align to int4
        float4 f = g_pos4[g_csr_i[e]];
        a0 += f.x; a1 += f.y; a2 += f.z;
    }
    for (; e + 4 <= end; e += 4) {
        int4 s4 = *(const int4*)(g_csr_i + e);
        float4 f0 = g_pos4[s4.x];
        float4 f1 = g_pos4[s4.y];
        float4 f2 = g_pos4[s4.z];
        float4 f3 = g_pos4[s4.w];
        a0 += (f0.x + f1.x) + (f2.x + f3.x);
        a1 += (f0.y + f1.y) + (f2.y + f3.y);
        a2 += (f0.z + f1.z) + (f2.z + f3.z);
    }
    for (; e < end; e++) {
        float4 f = g_pos4[g_csr_i[e]];
        a0 += f.x; a1 += f.y; a2 += f.z;
    }
    float di = g_dinv[v];
    a0 *= di; a1 *= di; a2 *= di;
    u64 xx0 = pack2(a0, a0), xx1 = pack2(a1, a1), xx2 = pack2(a2, a2);
    const u64* w0 = (const u64*)sW;
    const u64* w1 = (const u64*)(sW + 64);
    const u64* w2 = (const u64*)(sW + 128);
    const u64* bb = (const u64*)sb;
    __half2 tmp[32];
#pragma unroll
    for (int j2 = 0; j2 < 32; j2++) {
        u64 c = bb[j2];
        c = fma2(xx0, w0[j2], c);
        c = fma2(xx1, w1[j2], c);
        c = fma2(xx2, w2[j2], c);
        float lo, hi;
        unpack2(c, lo, hi);
        tmp[j2] = __floats2half2_rn(di * fmaxf(lo, 0.0f), di * fmaxf(hi, 0.0f));
    }
    uint4* o = (uint4*)(h1 + (long long)v * 64);
    const uint4* src = (const uint4*)tmp;
#pragma unroll
    for (int j = 0; j < 8; j++) o[j] = src[j];
}

// ---------------- layer 2+3: gather(fp16) + GEMM64x64 + ReLU + GEMM64x24 ------
#define L2_NPB 64   // nodes per block: 8 warps x 2 nodes x 4 iterations
__global__ void __launch_bounds__(256)
layer2_kernel(const __half* __restrict__ h1, const float* __restrict__ W2,
              const float* __restrict__ b2, const float* __restrict__ W3,
              __half* __restrict__ y) {
    __shared__ __align__(16) float sW2[64 * 64];
    __shared__ __align__(16) float sW3[64 * 24];
    __shared__ __align__(16) float sb2[64];
    __shared__ __align__(16) float tile[16][64];
    int t = threadIdx.x;
    for (int i = t; i < 64 * 64; i += 256) sW2[i] = W2[i];
    for (int i = t; i < 64 * 24; i += 256) sW3[i] = W3[i];
    if (t < 64) sb2[t] = b2[t];
    __syncthreads();
    int warp = t >> 5, lane = t & 31;
    int half = lane >> 4, q = lane & 15;
    const u64* w2p = (const u64*)sW2;   // 32 u64 per k-row
    const u64* w3p = (const u64*)sW3;   // 12 u64 per k-row
#pragma unroll
    for (int it = 0; it < L2_NPB / 16; it++) {
        int vbase = blockIdx.x * L2_NPB + it * 16 + warp * 2;
        int v = vbase + half;
        // ---- gather (half-warp per node, 4 halves per lane, fp32 accum) ----
        float4 a = make_float4(0.0f, 0.0f, 0.0f, 0.0f);
        if (v < N_NODES) {
            float di = g_dinv[v];
            {
                uint2 u = ((const uint2*)(h1 + (long long)v * 64))[q];
                float2 fa = __half22float2(*(__half2*)&u.x);
                float2 fb = __half22float2(*(__half2*)&u.y);
                a = make_float4(fa.x, fa.y, fb.x, fb.y);
            }
            int e = g_row_ptr[v], end = g_row_ptr[v + 1];
            for (; e + 2 <= end; e += 2) {
                int s0 = g_csr_i[e], s1 = g_csr_i[e + 1];
                uint2 u0 = ((const uint2*)(h1 + (long long)s0 * 64))[q];
                uint2 u1 = ((const uint2*)(h1 + (long long)s1 * 64))[q];
                float2 fa0 = __half22float2(*(__half2*)&u0.x);
                float2 fb0 = __half22float2(*(__half2*)&u0.y);
                float2 fa1 = __half22float2(*(__half2*)&u1.x);
                float2 fb1 = __half22float2(*(__half2*)&u1.y);
                a.x += fa0.x + fa1.x;
                a.y += fa0.y + fa1.y;
                a.z += fb0.x + fb1.x;
                a.w += fb0.y + fb1.y;
            }
            if (e < end) {
                uint2 u = ((const uint2*)(h1 + (long long)g_csr_i[e] * 64))[q];
                float2 fa = __half22float2(*(__half2*)&u.x);
                float2 fb = __half22float2(*(__half2*)&u.y);
                a.x += fa.x; a.y += fa.y; a.z += fb.x; a.w += fb.y;
            }
            a.x *= di; a.y *= di; a.z *= di; a.w *= di;
        }
        ((float4*)tile[warp * 2 + half])[q] = a;
        __syncwarp();
        // ---- W2 GEMM + ReLU: warp handles its 2 nodes sequentially ----
#pragma unroll
        for (int s = 0; s < 2; s++) {
            int vv = vbase + s;
            if (vv >= N_NODES) continue;
            float dvv = g_dinv[vv];
            float* row = tile[warp * 2 + s];
            u64 c01 = ((const u64*)sb2)[lane];
#pragma unroll
            for (int k4 = 0; k4 < 16; k4++) {
                float4 xv = ((const float4*)row)[k4];
                float xs[4] = {xv.x, xv.y, xv.z, xv.w};
#pragma unroll
                for (int kk = 0; kk < 4; kk++) {
                    u64 xx = pack2(xs[kk], xs[kk]);
                    c01 = fma2(xx, w2p[(k4 * 4 + kk) * 32 + lane], c01);
                }
            }
            float c0, c1;
            unpack2(c01, c0, c1);
            c0 = dvv * fmaxf(c0, 0.0f);
            c1 = dvv * fmaxf(c1, 0.0f);
            __syncwarp();
            ((float2*)row)[lane] = make_float2(c0, c1);
            __syncwarp();
        }
        // ---- W3 GEMM: both nodes concurrently (lanes 0-11 / 16-27) ----
        {
            int vv = vbase + half;
            if (vv < N_NODES && q < 12) {
                float* row = tile[warp * 2 + half];
                u64 acc = 0ULL;
#pragma unroll
                for (int k4 = 0; k4 < 16; k4++) {
                    float4 xv = ((const float4*)row)[k4];
                    float xs[4] = {xv.x, xv.y, xv.z, xv.w};
#pragma unroll
                    for (int kk = 0; kk < 4; kk++) {
                        u64 xx = pack2(xs[kk], xs[kk]);
                        acc = fma2(xx, w3p[(k4 * 4 + kk) * 12 + q], acc);
                    }
                }
                float y0, y1;
                unpack2(acc, y0, y1);
                ((__half2*)(y + (long long)vv * 32))[q] = __floats2half2_rn(y0, y1);
            }
            __syncwarp();
        }
    }
}

// ---------------- layer 3 aggregate + pooling + fused final -------------------
__global__ void __launch_bounds__(256)
gather_pool_final_kernel(const __half* __restrict__ y, const float* __restrict__ b3,
                         float* __restrict__ out, int nblocks) {
    int t = threadIdx.x;
    int warp = t >> 5, lane = t & 31;
    int grp = lane >> 4, l = lane & 15;
    bool act = l < 12;
    int vbeg = (blockIdx.x * 8 + warp) * 8;
    if (vbeg < N_NODES) {
        float2 acc = make_float2(0.0f, 0.0f);
        int curg = -1;
#pragma unroll 1
        for (int u = 0; u < 8; u++) {
            int v = vbeg + u;
            if (v >= N_NODES) break;
            float2 a = make_float2(0.0f, 0.0f);
            int e0 = g_row_ptr[v], e1 = g_row_ptr[v + 1];
            for (int e = e0 + grp; e < e1; e += 2) {
                if (act) {
                    int s = g_csr_i[e];
                    float2 f = __half22float2(((const __half2*)(y + (long long)s * 32))[l]);
                    a.x += f.x; a.y += f.y;
                }
            }
            a.x += __shfl_xor_sync(0xFFFFFFFFu, a.x, 16);
            a.y += __shfl_xor_sync(0xFFFFFFFFu, a.y, 16);
            if (grp == 0 && act) {
                float2 sf = __half22float2(((const __half2*)(y + (long long)v * 32))[l]);
                a.x += sf.x; a.y += sf.y;
                float dv = g_dinv[v];
                a.x *= dv; a.y *= dv;
                int g = g_batch[v];
                if (g != curg) {
                    if (curg >= 0) {
                        atomicAdd(&g_sums[curg * 24 + 2 * l], acc.x);
                        atomicAdd(&g_sums[curg * 24 + 2 * l + 1], acc.y);
                    }
                    curg = g;
                    acc = a;
                } else {
                    acc.x += a.x;
                    acc.y += a.y;
                }
            }
        }
        if (grp == 0 && act && curg >= 0) {
            atomicAdd(&g_sums[curg * 24 + 2 * l], acc.x);
            atomicAdd(&g_sums[curg * 24 + 2 * l + 1], acc.y);
        }
    }
    __syncthreads();
    __shared__ int s_last;
    if (t == 0) {
        __threadfence();
        int old = atomicAdd(&g_done, 1);
        s_last = (old == nblocks - 1) ? 1 : 0;
    }
    __syncthreads();
    if (s_last) {
        __threadfence();
        for (int i = t; i < N_GRAPHS * 24; i += 256) {
            int g = i / 24, j = i % 24;
            float c = g_cnt[g];
            float m = (c > 0.0f) ? (g_sums[i] / c + b3[j]) : 0.0f;
            out[i] = tanhf(m);
        }
        __syncthreads();
        for (int i = t; i < N_GRAPHS * 24; i += 256) g_sums[i] = 0.0f;
        if (t < N_GRAPHS) g_cnt[t] = 0.0f;
        if (t < N_SCANB) g_scan_flag[t] = 0ULL;
        if (t == 0) g_done = 0;
    }
}

// ---------------- launch -----------------------------------------------------
extern "C" void kernel_launch(void* const* d_in, const int* in_sizes, int n_in,
                              void* d_out, int out_size) {
    const float* pos   = (const float*)d_in[0];
    const int*   ei    = (const int*)d_in[1];   // int32 or int64 (detected)
    const int*   batch = (const int*)d_in[2];
    const float* W1    = (const float*)d_in[3];
    const float* b1    = (const float*)d_in[4];
    const float* W2    = (const float*)d_in[5];
    const float* b2    = (const float*)d_in[6];
    const float* W3    = (const float*)d_in[7];
    const float* b3    = (const float*)d_in[8];
    float*       out   = (float*)d_out;

    const int E = in_sizes[1] / 2;

    __half* h1; cudaGetSymbolAddress((void**)&h1, g_h16);
    __half* y;  cudaGetSymbolAddress((void**)&y, g_y16);

    const int TB = 256;
    auto grid = [&](long long n, int tb) { return (int)((n + tb - 1) / tb); };

    int pool_blocks = grid(N_NODES, 64);   // 8 warps/block x 8 nodes/warp

    prep_kernel<<<grid(E, TB), TB>>>(ei, batch, E);                           // #1
    scan_kernel<<<N_SCANB, SCAN_B>>>(pos, E);                                 // #2
    fill_csr_kernel<<<grid(E, TB), TB>>>(ei, E);                              // #3
    layer1_kernel<<<grid(N_NODES, 256), 256>>>(W1, b1, h1);                   // #4 (profiled)
    layer2_kernel<<<grid(N_NODES, L2_NPB), 256>>>(h1, W2, b2, W3, y);         // #5
    gather_pool_final_kernel<<<pool_blocks, 256>>>(y, b3, out, pool_blocks);  // #6
}